// round 1
// baseline (speedup 1.0000x reference)
#include <cuda_runtime.h>

#define C_     192
#define C3     576
#define NHEADS 6
#define HD     32
#define HH_    256
#define WW_    256
#define HW_    65536
#define BATCH  2

#define GR_CHUNKS 32
#define GR_TILES  16   // tiles of 128 cols per block => 2048 cols/block

// Scratch (device globals: allocation-free per harness rules)
__device__ float g_qkv[BATCH * C3 * HW_];          // 1x1 conv output (302 MB)
__device__ float g_dw [BATCH * C3 * HW_];          // depthwise output (302 MB)
__device__ float g_gram_part[GR_CHUNKS * BATCH * NHEADS * HD * HD];
__device__ float g_qsq_part [GR_CHUNKS * BATCH * NHEADS * HD];
__device__ float g_ksq_part [GR_CHUNKS * BATCH * NHEADS * HD];
__device__ float g_attn[BATCH * NHEADS * HD * HD];
__device__ float g_meff[BATCH * C_ * C_];

// ---------------------------------------------------------------------------
// Register-blocked SGEMM: C[M,N] = A[M,K] * B[K,N], row-major, fp32.
// BM=BN=128, BK=8, 256 threads, 8x8 per thread. K % 8 == 0, N % 128 == 0.
// ---------------------------------------------------------------------------
__global__ __launch_bounds__(256) void sgemm128(
    const float* __restrict__ A, const float* __restrict__ B, float* __restrict__ C,
    int M, int K, int N, long aBatch, long bBatch, long cBatch)
{
    A += (long)blockIdx.z * aBatch;
    B += (long)blockIdx.z * bBatch;
    C += (long)blockIdx.z * cBatch;

    const int m0 = blockIdx.y * 128;
    const int n0 = blockIdx.x * 128;

    __shared__ float As[8][128];
    __shared__ float Bs[8][128];

    const int tid = threadIdx.x;
    const int tx = tid & 15;        // 0..15  (N direction, 8 cols each)
    const int ty = tid >> 4;        // 0..15  (M direction, 8 rows each)

    const int arow = tid >> 1;          // 0..127
    const int acol = (tid & 1) * 4;     // 0 or 4
    const int brow = tid >> 5;          // 0..7
    const int bcol = (tid & 31) * 4;    // 0..124

    float acc[8][8];
    #pragma unroll
    for (int i = 0; i < 8; i++)
        #pragma unroll
        for (int j = 0; j < 8; j++) acc[i][j] = 0.f;

    for (int k0 = 0; k0 < K; k0 += 8) {
        float4 a4 = make_float4(0.f, 0.f, 0.f, 0.f);
        if (m0 + arow < M)
            a4 = *reinterpret_cast<const float4*>(A + (long)(m0 + arow) * K + k0 + acol);
        float4 b4 = *reinterpret_cast<const float4*>(B + (long)(k0 + brow) * N + n0 + bcol);

        __syncthreads();
        As[acol + 0][arow] = a4.x;
        As[acol + 1][arow] = a4.y;
        As[acol + 2][arow] = a4.z;
        As[acol + 3][arow] = a4.w;
        *reinterpret_cast<float4*>(&Bs[brow][bcol]) = b4;
        __syncthreads();

        #pragma unroll
        for (int kk = 0; kk < 8; kk++) {
            float ar[8], br[8];
            #pragma unroll
            for (int i = 0; i < 4; i++) {
                float4 t = *reinterpret_cast<const float4*>(&As[kk][ty * 8 + i * 4]);
                ar[i*4+0]=t.x; ar[i*4+1]=t.y; ar[i*4+2]=t.z; ar[i*4+3]=t.w;
                // (only two float4 loads: i = 0..1)
                if (i == 1) break;
            }
            {
                float4 t0 = *reinterpret_cast<const float4*>(&As[kk][ty * 8]);
                float4 t1 = *reinterpret_cast<const float4*>(&As[kk][ty * 8 + 4]);
                ar[0]=t0.x; ar[1]=t0.y; ar[2]=t0.z; ar[3]=t0.w;
                ar[4]=t1.x; ar[5]=t1.y; ar[6]=t1.z; ar[7]=t1.w;
            }
            {
                float4 t0 = *reinterpret_cast<const float4*>(&Bs[kk][tx * 8]);
                float4 t1 = *reinterpret_cast<const float4*>(&Bs[kk][tx * 8 + 4]);
                br[0]=t0.x; br[1]=t0.y; br[2]=t0.z; br[3]=t0.w;
                br[4]=t1.x; br[5]=t1.y; br[6]=t1.z; br[7]=t1.w;
            }
            #pragma unroll
            for (int i = 0; i < 8; i++)
                #pragma unroll
                for (int j = 0; j < 8; j++)
                    acc[i][j] += ar[i] * br[j];
        }
    }

    #pragma unroll
    for (int i = 0; i < 8; i++) {
        int row = m0 + ty * 8 + i;
        if (row < M) {
            float4 v0 = make_float4(acc[i][0], acc[i][1], acc[i][2], acc[i][3]);
            float4 v1 = make_float4(acc[i][4], acc[i][5], acc[i][6], acc[i][7]);
            *reinterpret_cast<float4*>(C + (long)row * N + n0 + tx * 8)     = v0;
            *reinterpret_cast<float4*>(C + (long)row * N + n0 + tx * 8 + 4) = v1;
        }
    }
}

// ---------------------------------------------------------------------------
// Depthwise 3x3, padding=1 (cross-correlation, matching lax.conv).
// One thread per output pixel.
// ---------------------------------------------------------------------------
__global__ __launch_bounds__(256) void dwconv3x3(
    const float* __restrict__ in, const float* __restrict__ wdw, float* __restrict__ out)
{
    long idx = (long)blockIdx.x * 256 + threadIdx.x;   // < BATCH*C3*HW
    int pix = (int)(idx & (HW_ - 1));
    long bc  = idx >> 16;
    int c   = (int)(bc % C3);
    int y = pix >> 8;
    int x = pix & 255;

    const float* w = wdw + c * 9;
    const float* p = in + bc * (long)HW_;

    float w00 = w[0], w01 = w[1], w02 = w[2];
    float w10 = w[3], w11 = w[4], w12 = w[5];
    float w20 = w[6], w21 = w[7], w22 = w[8];

    float s = 0.f;
    if (y > 0 && y < HH_ - 1 && x > 0 && x < WW_ - 1) {
        const float* r0 = p + (y - 1) * WW_ + x;
        const float* r1 = r0 + WW_;
        const float* r2 = r1 + WW_;
        s = w00 * r0[-1] + w01 * r0[0] + w02 * r0[1]
          + w10 * r1[-1] + w11 * r1[0] + w12 * r1[1]
          + w20 * r2[-1] + w21 * r2[0] + w22 * r2[1];
    } else {
        #pragma unroll
        for (int dy = -1; dy <= 1; dy++) {
            int yy = y + dy;
            if (yy < 0 || yy >= HH_) continue;
            #pragma unroll
            for (int dx = -1; dx <= 1; dx++) {
                int xx = x + dx;
                if (xx < 0 || xx >= WW_) continue;
                s += w[(dy + 1) * 3 + (dx + 1)] * p[yy * WW_ + xx];
            }
        }
    }
    out[idx] = s;
}

// ---------------------------------------------------------------------------
// Gram: per (b, head) compute partial G = Q K^T (32x32) over a chunk of HW,
// plus partial row sum-squares of Q and K (for L2 normalization).
// grid = (GR_CHUNKS, BATCH*NHEADS), 1024 threads: thread (d,e) owns G[d][e].
// ---------------------------------------------------------------------------
__global__ __launch_bounds__(1024) void gram_kernel(const float* __restrict__ dw)
{
    __shared__ float qs[32][128];
    __shared__ float ks[128][33];   // padded: transposed K tile

    const int bh = blockIdx.y;                 // 0..11
    const int b = bh / NHEADS, h = bh % NHEADS;
    const float* qp = dw + (long)b * C3 * HW_ + (long)(h * HD) * HW_;
    const float* kp = dw + (long)b * C3 * HW_ + (long)(C_ + h * HD) * HW_;

    const int tid = threadIdx.x;
    const int d = tid >> 5;        // 0..31
    const int e = tid & 31;        // 0..31
    const int lcol = tid & 127;    // loader col
    const int lrow = tid >> 7;     // loader row 0..7

    float acc = 0.f, qsq = 0.f, ksq = 0.f;
    const int base0 = blockIdx.x * (GR_TILES * 128);

    for (int t = 0; t < GR_TILES; t++) {
        const int base = base0 + t * 128;
        __syncthreads();
        #pragma unroll
        for (int r = 0; r < 4; r++) {
            int row = lrow + 8 * r;
            qs[row][lcol] = qp[(long)row * HW_ + base + lcol];
            ks[lcol][row] = kp[(long)row * HW_ + base + lcol];
        }
        __syncthreads();

        #pragma unroll 8
        for (int n = 0; n < 128; n++)
            acc += qs[d][n] * ks[n][e];

        // distributed sum-squares: warp d handles q-row d and k-row d
        #pragma unroll
        for (int j = 0; j < 4; j++) {
            float qv = qs[d][e + 32 * j];
            qsq += qv * qv;
            float kv = ks[e + 32 * j][d];
            ksq += kv * kv;
        }
    }

    g_gram_part[(long)blockIdx.x * (BATCH * NHEADS * HD * HD) + bh * 1024 + d * 32 + e] = acc;

    #pragma unroll
    for (int o = 16; o > 0; o >>= 1) {
        qsq += __shfl_xor_sync(0xffffffffu, qsq, o);
        ksq += __shfl_xor_sync(0xffffffffu, ksq, o);
    }
    if (e == 0) {
        g_qsq_part[blockIdx.x * (BATCH * NHEADS * HD) + bh * HD + d] = qsq;
        g_ksq_part[blockIdx.x * (BATCH * NHEADS * HD) + bh * HD + d] = ksq;
    }
}

// ---------------------------------------------------------------------------
// Reduce partials, normalize, apply temperature, softmax over e.
// grid = BATCH*NHEADS blocks of (32,32): x=e, y=d. Warp == row d.
// ---------------------------------------------------------------------------
__global__ __launch_bounds__(1024) void attn_kernel(const float* __restrict__ temperature)
{
    const int bh = blockIdx.x;
    const int h = bh % NHEADS;
    const int e = threadIdx.x, d = threadIdx.y;

    float g = 0.f, qsq = 0.f, ksq = 0.f;
    #pragma unroll
    for (int ch = 0; ch < GR_CHUNKS; ch++) {
        g   += g_gram_part[(long)ch * (BATCH * NHEADS * HD * HD) + bh * 1024 + d * 32 + e];
        qsq += g_qsq_part[ch * (BATCH * NHEADS * HD) + bh * HD + d];
        ksq += g_ksq_part[ch * (BATCH * NHEADS * HD) + bh * HD + e];
    }

    float t  = fminf(temperature[h], 5.0f);
    float qn = fmaxf(sqrtf(qsq), 1e-12f);
    float kn = fmaxf(sqrtf(ksq), 1e-12f);
    float val = g / (qn * kn) * t;

    float m = val;
    #pragma unroll
    for (int o = 16; o > 0; o >>= 1)
        m = fmaxf(m, __shfl_xor_sync(0xffffffffu, m, o));
    float p = expf(val - m);
    float s = p;
    #pragma unroll
    for (int o = 16; o > 0; o >>= 1)
        s += __shfl_xor_sync(0xffffffffu, s, o);

    g_attn[bh * 1024 + d * 32 + e] = p / s;
}

// ---------------------------------------------------------------------------
// M_eff[b][o][h*32+e] = sum_d w_proj[o][h*32+d] * attn[b,h,d,e]
// Folds proj into the attn*v GEMM (block-diagonal absorb).
// ---------------------------------------------------------------------------
__global__ __launch_bounds__(256) void meff_kernel(const float* __restrict__ wproj)
{
    const int idx = blockIdx.x * 256 + threadIdx.x;   // 0..36863
    const int bz = blockIdx.y;
    const int o  = idx / C_;
    const int ce = idx % C_;
    const int h  = ce >> 5, e = ce & 31;

    const float* ar = g_attn + (bz * NHEADS + h) * 1024 + e;  // attn[d*32+e]
    const float* wr = wproj + o * C_ + h * 32;

    float s = 0.f;
    #pragma unroll
    for (int dd = 0; dd < 32; dd++)
        s += wr[dd] * ar[dd * 32];

    g_meff[(long)bz * C_ * C_ + idx] = s;
}

// ---------------------------------------------------------------------------
extern "C" void kernel_launch(void* const* d_in, const int* in_sizes, int n_in,
                              void* d_out, int out_size)
{
    (void)in_sizes; (void)n_in; (void)out_size;
    const float* x      = (const float*)d_in[0];
    const float* w_qkv  = (const float*)d_in[1];
    const float* w_dw   = (const float*)d_in[2];
    const float* w_proj = (const float*)d_in[3];
    const float* temp   = (const float*)d_in[4];
    float* out = (float*)d_out;

    float *qkv, *dw, *meff;
    cudaGetSymbolAddress((void**)&qkv,  g_qkv);
    cudaGetSymbolAddress((void**)&dw,   g_dw);
    cudaGetSymbolAddress((void**)&meff, g_meff);

    // 1) qkv = w_qkv @ x   (576 x 192 x 65536, per batch)
    sgemm128<<<dim3(HW_ / 128, (C3 + 127) / 128, BATCH), 256>>>(
        w_qkv, x, qkv, C3, C_, HW_, 0L, (long)C_ * HW_, (long)C3 * HW_);

    // 2) depthwise 3x3
    dwconv3x3<<<(BATCH * C3 * HW_) / 256, 256>>>(qkv, w_dw, dw);

    // 3) Gram + sum-squares partials
    gram_kernel<<<dim3(GR_CHUNKS, BATCH * NHEADS), 1024>>>(dw);

    // 4) normalize + temperature + softmax
    attn_kernel<<<BATCH * NHEADS, dim3(32, 32)>>>(temp);

    // 5) M_eff = w_proj @ blockdiag(attn)
    meff_kernel<<<dim3((C_ * C_) / 256, BATCH), 256>>>(w_proj);

    // 6) out = M_eff @ v   (192 x 192 x 65536, per batch; v = dw channels 384..575)
    sgemm128<<<dim3(HW_ / 128, (C_ + 127) / 128, BATCH), 256>>>(
        meff, dw + (long)2 * C_ * HW_, out, C_, C_, HW_,
        (long)C_ * C_, (long)C3 * HW_, (long)C_ * HW_);
}

// round 3
// speedup vs baseline: 1.2702x; 1.2702x over previous
#include <cuda_runtime.h>
#include <cuda_bf16.h>
#include <cstdint>

#define C_     192
#define C3     576
#define NHEADS 6
#define HD     32
#define HH_    256
#define WW_    256
#define HW_    65536
#define BATCH  2
#define KDIM   192
#define M1     576
#define M1PAD  640
#define M2     192
#define M2PAD  256

#define GR_CHUNKS 32
#define GR_TILES  16

// GEMM tiling
#define BM 128
#define BN 128
#define BK 32
#define PADB 144                 // bytes per smem tile row (9 x 16B -> conflict-free ldmatrix)
#define ATILE (BM * PADB)        // 18432 B
#define BTILE (BN * PADB)        // 18432 B
#define BUFSZ (ATILE + BTILE)    // 36864 B
#define GSMEM (2 * BUFSZ)        // 73728 B
#define NITER 18                 // 3 passes * (192/32)

// ---------------- scratch (device globals; zero-initialized at load) --------
__device__ float g_qkv[BATCH * C3 * HW_];
__device__ float g_dw [BATCH * C3 * HW_];
__device__ __nv_bfloat16 g_xT_h[BATCH * HW_ * KDIM];
__device__ __nv_bfloat16 g_xT_l[BATCH * HW_ * KDIM];
__device__ __nv_bfloat16 g_vT_h[BATCH * HW_ * KDIM];
__device__ __nv_bfloat16 g_vT_l[BATCH * HW_ * KDIM];
__device__ __nv_bfloat16 g_A1_h[M1PAD * KDIM];   // padded rows stay zero
__device__ __nv_bfloat16 g_A1_l[M1PAD * KDIM];
__device__ __nv_bfloat16 g_A2_h[BATCH * M2PAD * KDIM];
__device__ __nv_bfloat16 g_A2_l[BATCH * M2PAD * KDIM];
__device__ float g_gram_part[GR_CHUNKS * BATCH * NHEADS * HD * HD];
__device__ float g_qsq_part [GR_CHUNKS * BATCH * NHEADS * HD];
__device__ float g_ksq_part [GR_CHUNKS * BATCH * NHEADS * HD];
__device__ float g_attn[BATCH * NHEADS * HD * HD];

// ---------------- PTX helpers (sm_80+ only; no 'a' features) -----------------
__device__ __forceinline__ uint32_t smem_u32(const void* p) {
    uint32_t a;
    asm("{ .reg .u64 t; cvta.to.shared.u64 t, %1; cvt.u32.u64 %0, t; }" : "=r"(a) : "l"(p));
    return a;
}
#define CP_ASYNC16(dst, src) \
    asm volatile("cp.async.cg.shared.global [%0], [%1], 16;" :: "r"(dst), "l"(src))
#define CP_COMMIT() asm volatile("cp.async.commit_group;" ::: "memory")
#define CP_WAIT(n)  asm volatile("cp.async.wait_group %0;" :: "n"(n) : "memory")

#define LDM_X4(r, addr) \
    asm volatile("ldmatrix.sync.aligned.m8n8.x4.shared.b16 {%0,%1,%2,%3}, [%4];" \
        : "=r"((r)[0]), "=r"((r)[1]), "=r"((r)[2]), "=r"((r)[3]) : "r"(addr))
#define LDM_X2(r, addr) \
    asm volatile("ldmatrix.sync.aligned.m8n8.x2.shared.b16 {%0,%1}, [%2];" \
        : "=r"((r)[0]), "=r"((r)[1]) : "r"(addr))

__device__ __forceinline__ void mma16816(float* d, const uint32_t* a, const uint32_t* b) {
    asm volatile(
        "mma.sync.aligned.m16n8k16.row.col.f32.bf16.bf16.f32 "
        "{%0,%1,%2,%3}, {%4,%5,%6,%7}, {%8,%9}, {%0,%1,%2,%3};"
        : "+f"(d[0]), "+f"(d[1]), "+f"(d[2]), "+f"(d[3])
        : "r"(a[0]), "r"(a[1]), "r"(a[2]), "r"(a[3]), "r"(b[0]), "r"(b[1]));
}

// ---------------------------------------------------------------------------
// bf16 split GEMM via mma.sync: C[M,N] = A*B^T with A[M][192], B[N][192]
// hi/lo pre-split; 3 products: Ah*Bh + Ah*Bl + Al*Bh.
// grid = (Mpad/128, HW/128, BATCH), 256 threads, dyn smem = GSMEM.
// ---------------------------------------------------------------------------
__global__ __launch_bounds__(256, 1) void gemm_mma(
    const __nv_bfloat16* __restrict__ Ah, const __nv_bfloat16* __restrict__ Al,
    const __nv_bfloat16* __restrict__ Bh, const __nv_bfloat16* __restrict__ Bl,
    float* __restrict__ C, int Mvalid, long aBatch, long cBatch)
{
    extern __shared__ char smem[];
    const uint32_t sb = smem_u32(smem);

    const int tid  = threadIdx.x;
    const int wid  = tid >> 5;
    const int lane = tid & 31;
    const int wm   = wid >> 2;       // 0..1  (64 rows each)
    const int wn   = wid & 3;        // 0..3  (32 cols each)

    const int bz = blockIdx.z;
    const int m0 = blockIdx.x * BM;
    const int n0 = blockIdx.y * BN;

    Ah += (long)bz * aBatch;  Al += (long)bz * aBatch;
    Bh += (long)bz * HW_ * KDIM;  Bl += (long)bz * HW_ * KDIM;
    C  += (long)bz * cBatch;

    float acc[4][4][4];
    #pragma unroll
    for (int i = 0; i < 4; i++)
        #pragma unroll
        for (int j = 0; j < 4; j++)
            #pragma unroll
            for (int r = 0; r < 4; r++) acc[i][j][r] = 0.f;

    // loader indices: 2 chunks of A + 2 chunks of B per thread per iter
    const int lrow0 = tid >> 2;            // 0..63
    const int lc    = tid & 3;             // 16B chunk within 64B of K-tile

    auto loadTiles = [&](int it, int buf) {
        const int pass = it / 6;
        const int k0   = (it % 6) * BK;
        const __nv_bfloat16* As = (pass == 2) ? Al : Ah;
        const __nv_bfloat16* Bs = (pass == 1) ? Bl : Bh;
        const uint32_t abase = sb + (uint32_t)buf * BUFSZ;
        const uint32_t bbase = abase + ATILE;
        #pragma unroll
        for (int i = 0; i < 2; i++) {
            const int row = lrow0 + 64 * i;
            const uint32_t soff = (uint32_t)row * PADB + lc * 16;
            CP_ASYNC16(abase + soff, As + (long)(m0 + row) * KDIM + k0 + lc * 8);
            CP_ASYNC16(bbase + soff, Bs + (long)(n0 + row) * KDIM + k0 + lc * 8);
        }
    };

    loadTiles(0, 0);
    CP_COMMIT();

    #pragma unroll 1
    for (int it = 0; it < NITER; it++) {
        if (it + 1 < NITER) {
            loadTiles(it + 1, (it + 1) & 1);
            CP_COMMIT();
            CP_WAIT(1);
        } else {
            CP_WAIT(0);
        }
        __syncthreads();

        const uint32_t abase = sb + (uint32_t)(it & 1) * BUFSZ;
        const uint32_t bbase = abase + ATILE;

        #pragma unroll
        for (int kf = 0; kf < 2; kf++) {
            uint32_t a[4][4], b[4][2];
            #pragma unroll
            for (int i = 0; i < 4; i++) {
                uint32_t addr = abase
                    + (uint32_t)(wm * 64 + i * 16 + (lane & 15)) * PADB
                    + kf * 32 + ((lane >> 4) << 4);
                LDM_X4(a[i], addr);
            }
            #pragma unroll
            for (int j = 0; j < 4; j++) {
                uint32_t addr = bbase
                    + (uint32_t)(wn * 32 + j * 8 + (lane & 7)) * PADB
                    + kf * 32 + (((lane >> 3) & 1) << 4);
                LDM_X2(b[j], addr);
            }
            #pragma unroll
            for (int i = 0; i < 4; i++)
                #pragma unroll
                for (int j = 0; j < 4; j++)
                    mma16816(acc[i][j], a[i], b[j]);
        }
        __syncthreads();
    }

    // epilogue
    const int rw = m0 + wm * 64 + (lane >> 2);
    const int cw = n0 + wn * 32 + (lane & 3) * 2;
    #pragma unroll
    for (int i = 0; i < 4; i++) {
        #pragma unroll
        for (int j = 0; j < 4; j++) {
            const int row = rw + i * 16;
            const int col = cw + j * 8;
            if (row < Mvalid)
                *reinterpret_cast<float2*>(C + (long)row * HW_ + col) =
                    make_float2(acc[i][j][0], acc[i][j][1]);
            if (row + 8 < Mvalid)
                *reinterpret_cast<float2*>(C + (long)(row + 8) * HW_ + col) =
                    make_float2(acc[i][j][2], acc[i][j][3]);
        }
    }
}

// ---------------------------------------------------------------------------
// Transpose + split fp32 [K=192][HW] -> bf16 hi/lo [HW][192]
// ---------------------------------------------------------------------------
__global__ __launch_bounds__(256) void transpose_split(
    const float* __restrict__ in, __nv_bfloat16* __restrict__ oh,
    __nv_bfloat16* __restrict__ ol, long inBatchStride)
{
    __shared__ float t[32][33];
    const int b = blockIdx.z;
    const float* p = in + (long)b * inBatchStride;
    const int n0 = blockIdx.x * 32, k0 = blockIdx.y * 32;
    const int tx = threadIdx.x, ty = threadIdx.y;   // (32, 8)

    #pragma unroll
    for (int i = 0; i < 4; i++)
        t[ty + 8 * i][tx] = p[(long)(k0 + ty + 8 * i) * HW_ + n0 + tx];
    __syncthreads();
    #pragma unroll
    for (int i = 0; i < 4; i++) {
        const int n = n0 + ty + 8 * i, k = k0 + tx;
        float f = t[tx][ty + 8 * i];
        __nv_bfloat16 h = __float2bfloat16(f);
        __nv_bfloat16 l = __float2bfloat16(f - __bfloat162float(h));
        const long o = (long)b * HW_ * KDIM + (long)n * KDIM + k;
        oh[o] = h;  ol[o] = l;
    }
}

// split w_qkv (576x192 fp32) -> A1 hi/lo (padded 640x192)
__global__ __launch_bounds__(256) void split_w1(const float* __restrict__ w)
{
    const int i = blockIdx.x * 256 + threadIdx.x;   // < 576*192
    float f = w[i];
    __nv_bfloat16 h = __float2bfloat16(f);
    g_A1_h[i] = h;
    g_A1_l[i] = __float2bfloat16(f - __bfloat162float(h));
}

// ---------------------------------------------------------------------------
// Depthwise 3x3 pad=1
// ---------------------------------------------------------------------------
__global__ __launch_bounds__(256) void dwconv3x3(
    const float* __restrict__ in, const float* __restrict__ wdw, float* __restrict__ out)
{
    long idx = (long)blockIdx.x * 256 + threadIdx.x;
    int pix = (int)(idx & (HW_ - 1));
    long bc = idx >> 16;
    int c = (int)(bc % C3);
    int y = pix >> 8, x = pix & 255;

    const float* w = wdw + c * 9;
    const float* p = in + bc * (long)HW_;

    float s = 0.f;
    if (y > 0 && y < HH_ - 1 && x > 0 && x < WW_ - 1) {
        const float* r0 = p + (y - 1) * WW_ + x;
        const float* r1 = r0 + WW_;
        const float* r2 = r1 + WW_;
        s = w[0]*r0[-1] + w[1]*r0[0] + w[2]*r0[1]
          + w[3]*r1[-1] + w[4]*r1[0] + w[5]*r1[1]
          + w[6]*r2[-1] + w[7]*r2[0] + w[8]*r2[1];
    } else {
        #pragma unroll
        for (int dy = -1; dy <= 1; dy++) {
            int yy = y + dy;
            if (yy < 0 || yy >= HH_) continue;
            #pragma unroll
            for (int dx = -1; dx <= 1; dx++) {
                int xx = x + dx;
                if (xx < 0 || xx >= WW_) continue;
                s += w[(dy + 1) * 3 + (dx + 1)] * p[yy * WW_ + xx];
            }
        }
    }
    out[idx] = s;
}

// ---------------------------------------------------------------------------
// Gram partials (Q K^T per head) + sum-squares
// ---------------------------------------------------------------------------
__global__ __launch_bounds__(1024) void gram_kernel(const float* __restrict__ dw)
{
    __shared__ float qs[32][128];
    __shared__ float ks[128][33];

    const int bh = blockIdx.y;
    const int b = bh / NHEADS, h = bh % NHEADS;
    const float* qp = dw + (long)b * C3 * HW_ + (long)(h * HD) * HW_;
    const float* kp = dw + (long)b * C3 * HW_ + (long)(C_ + h * HD) * HW_;

    const int tid = threadIdx.x;
    const int d = tid >> 5, e = tid & 31;
    const int lcol = tid & 127, lrow = tid >> 7;

    float acc = 0.f, qsq = 0.f, ksq = 0.f;
    const int base0 = blockIdx.x * (GR_TILES * 128);

    for (int t = 0; t < GR_TILES; t++) {
        const int base = base0 + t * 128;
        __syncthreads();
        #pragma unroll
        for (int r = 0; r < 4; r++) {
            int row = lrow + 8 * r;
            qs[row][lcol] = qp[(long)row * HW_ + base + lcol];
            ks[lcol][row] = kp[(long)row * HW_ + base + lcol];
        }
        __syncthreads();

        #pragma unroll 8
        for (int n = 0; n < 128; n++)
            acc += qs[d][n] * ks[n][e];

        #pragma unroll
        for (int j = 0; j < 4; j++) {
            float qv = qs[d][e + 32 * j];  qsq += qv * qv;
            float kv = ks[e + 32 * j][d];  ksq += kv * kv;
        }
    }

    g_gram_part[(long)blockIdx.x * (BATCH*NHEADS*HD*HD) + bh * 1024 + d * 32 + e] = acc;
    #pragma unroll
    for (int o = 16; o > 0; o >>= 1) {
        qsq += __shfl_xor_sync(0xffffffffu, qsq, o);
        ksq += __shfl_xor_sync(0xffffffffu, ksq, o);
    }
    if (e == 0) {
        g_qsq_part[blockIdx.x * (BATCH*NHEADS*HD) + bh * HD + d] = qsq;
        g_ksq_part[blockIdx.x * (BATCH*NHEADS*HD) + bh * HD + d] = ksq;
    }
}

// reduce + normalize + temperature + softmax
__global__ __launch_bounds__(1024) void attn_kernel(const float* __restrict__ temperature)
{
    const int bh = blockIdx.x;
    const int h = bh % NHEADS;
    const int e = threadIdx.x, d = threadIdx.y;

    float g = 0.f, qsq = 0.f, ksq = 0.f;
    #pragma unroll
    for (int ch = 0; ch < GR_CHUNKS; ch++) {
        g   += g_gram_part[(long)ch * (BATCH*NHEADS*HD*HD) + bh * 1024 + d * 32 + e];
        qsq += g_qsq_part[ch * (BATCH*NHEADS*HD) + bh * HD + d];
        ksq += g_ksq_part[ch * (BATCH*NHEADS*HD) + bh * HD + e];
    }
    float t  = fminf(temperature[h], 5.0f);
    float qn = fmaxf(sqrtf(qsq), 1e-12f);
    float kn = fmaxf(sqrtf(ksq), 1e-12f);
    float val = g / (qn * kn) * t;

    float m = val;
    #pragma unroll
    for (int o = 16; o > 0; o >>= 1) m = fmaxf(m, __shfl_xor_sync(0xffffffffu, m, o));
    float p = expf(val - m);
    float s = p;
    #pragma unroll
    for (int o = 16; o > 0; o >>= 1) s += __shfl_xor_sync(0xffffffffu, s, o);

    g_attn[bh * 1024 + d * 32 + e] = p / s;
}

// M_eff = w_proj @ blockdiag(attn) -> pre-split bf16 A2 (padded 256x192/batch)
__global__ __launch_bounds__(256) void meff_kernel(const float* __restrict__ wproj)
{
    const int idx = blockIdx.x * 256 + threadIdx.x;   // 0..36863
    const int bz  = blockIdx.y;
    const int o   = idx / C_;
    const int ce  = idx % C_;
    const int h   = ce >> 5, e = ce & 31;

    const float* ar = g_attn + (bz * NHEADS + h) * 1024 + e;
    const float* wr = wproj + o * C_ + h * 32;

    float s = 0.f;
    #pragma unroll
    for (int dd = 0; dd < 32; dd++) s += wr[dd] * ar[dd * 32];

    __nv_bfloat16 hi = __float2bfloat16(s);
    const long oidx = (long)bz * M2PAD * KDIM + (long)o * KDIM + ce;
    g_A2_h[oidx] = hi;
    g_A2_l[oidx] = __float2bfloat16(s - __bfloat162float(hi));
}

// ---------------------------------------------------------------------------
extern "C" void kernel_launch(void* const* d_in, const int* in_sizes, int n_in,
                              void* d_out, int out_size)
{
    (void)in_sizes; (void)n_in; (void)out_size;
    const float* x      = (const float*)d_in[0];
    const float* w_qkv  = (const float*)d_in[1];
    const float* w_dw   = (const float*)d_in[2];
    const float* w_proj = (const float*)d_in[3];
    const float* temp   = (const float*)d_in[4];
    float* out = (float*)d_out;

    float *qkv, *dw;
    __nv_bfloat16 *xth, *xtl, *vth, *vtl, *a1h, *a1l, *a2h, *a2l;
    cudaGetSymbolAddress((void**)&qkv, g_qkv);
    cudaGetSymbolAddress((void**)&dw,  g_dw);
    cudaGetSymbolAddress((void**)&xth, g_xT_h);
    cudaGetSymbolAddress((void**)&xtl, g_xT_l);
    cudaGetSymbolAddress((void**)&vth, g_vT_h);
    cudaGetSymbolAddress((void**)&vtl, g_vT_l);
    cudaGetSymbolAddress((void**)&a1h, g_A1_h);
    cudaGetSymbolAddress((void**)&a1l, g_A1_l);
    cudaGetSymbolAddress((void**)&a2h, g_A2_h);
    cudaGetSymbolAddress((void**)&a2l, g_A2_l);

    static bool attr_set = false;
    if (!attr_set) {
        cudaFuncSetAttribute(gemm_mma, cudaFuncAttributeMaxDynamicSharedMemorySize, GSMEM);
        attr_set = true;
    }

    // 0) split weights
    split_w1<<<(M1 * KDIM) / 256, 256>>>(w_qkv);

    // 1) transpose+split x -> xT hi/lo [b][HW][192]
    transpose_split<<<dim3(HW_ / 32, KDIM / 32, BATCH), dim3(32, 8)>>>(
        x, xth, xtl, (long)C_ * HW_);

    // 2) qkv = w_qkv @ x   (mma.sync bf16 split)
    gemm_mma<<<dim3(M1PAD / BM, HW_ / BN, BATCH), 256, GSMEM>>>(
        a1h, a1l, xth, xtl, qkv, M1, 0L, (long)C3 * HW_);

    // 3) depthwise 3x3
    dwconv3x3<<<(BATCH * C3 * HW_) / 256, 256>>>(qkv, w_dw, dw);

    // 4) transpose+split v -> vT hi/lo
    transpose_split<<<dim3(HW_ / 32, KDIM / 32, BATCH), dim3(32, 8)>>>(
        dw + (long)2 * C_ * HW_, vth, vtl, (long)C3 * HW_);

    // 5) gram partials + attn + M_eff
    gram_kernel<<<dim3(GR_CHUNKS, BATCH * NHEADS), 1024>>>(dw);
    attn_kernel<<<BATCH * NHEADS, dim3(32, 32)>>>(temp);
    meff_kernel<<<dim3((C_ * C_) / 256, BATCH), 256>>>(w_proj);

    // 6) out = M_eff @ v   (mma.sync bf16 split)
    gemm_mma<<<dim3(M2PAD / BM, HW_ / BN, BATCH), 256, GSMEM>>>(
        a2h, a2l, vth, vtl, out, M2, (long)M2PAD * KDIM, (long)C_ * HW_);
}

// round 5
// speedup vs baseline: 1.5440x; 1.2156x over previous
#include <cuda_runtime.h>
#include <cuda_bf16.h>
#include <cstdint>

#define C_     192
#define C3     576
#define NHEADS 6
#define HD     32
#define HH_    256
#define WW_    256
#define HW_    65536
#define BATCH  2
#define KDIM   192
#define M1     576
#define M1PAD  640
#define M2     192
#define M2PAD  256

#define GR_CHUNKS 32           // 32 chunks x 8 rows = 256 image rows

// GEMM tiling
#define BM 128
#define BN 128
#define BK 32
#define APITCH 80              // bytes per A smem row (64B data + 16B pad)
#define BPITCH 272             // bytes per B smem row (256B data + 16B pad)
#define ATILE (BM * APITCH)    // 10240
#define BTILE (BK * BPITCH)    // 8704
#define BUFSZ (ATILE + BTILE)  // 18944
#define GSMEM (2 * BUFSZ)      // 37888
#define NITER 18               // 3 passes * (192/32)

#define DG_SMEM (2 * 32 * 258 * 4)   // 66048 B (qs + ks tiles)

// ---------------- scratch (device globals; zero-initialized at load) --------
__device__ float g_qkv[BATCH * C3 * HW_];
__device__ __nv_bfloat16 g_x_h[BATCH * KDIM * HW_];   // [b][k][n] natural layout
__device__ __nv_bfloat16 g_x_l[BATCH * KDIM * HW_];
__device__ __nv_bfloat16 g_v_h[BATCH * KDIM * HW_];
__device__ __nv_bfloat16 g_v_l[BATCH * KDIM * HW_];
__device__ __nv_bfloat16 g_A1_h[M1PAD * KDIM];        // padded rows stay zero
__device__ __nv_bfloat16 g_A1_l[M1PAD * KDIM];
__device__ __nv_bfloat16 g_A2_h[BATCH * M2PAD * KDIM];
__device__ __nv_bfloat16 g_A2_l[BATCH * M2PAD * KDIM];
__device__ float g_gram_part[GR_CHUNKS * BATCH * NHEADS * HD * HD];
__device__ float g_qsq_part [GR_CHUNKS * BATCH * NHEADS * HD];
__device__ float g_ksq_part [GR_CHUNKS * BATCH * NHEADS * HD];
__device__ float g_attn[BATCH * NHEADS * HD * HD];

// ---------------- PTX helpers (sm_80+ only) ----------------------------------
__device__ __forceinline__ uint32_t smem_u32(const void* p) {
    uint32_t a;
    asm("{ .reg .u64 t; cvta.to.shared.u64 t, %1; cvt.u32.u64 %0, t; }" : "=r"(a) : "l"(p));
    return a;
}
#define CP_ASYNC16(dst, src) \
    asm volatile("cp.async.cg.shared.global [%0], [%1], 16;" :: "r"(dst), "l"(src))
#define CP_COMMIT() asm volatile("cp.async.commit_group;" ::: "memory")
#define CP_WAIT(n)  asm volatile("cp.async.wait_group %0;" :: "n"(n) : "memory")

#define LDM_X4(r, addr) \
    asm volatile("ldmatrix.sync.aligned.m8n8.x4.shared.b16 {%0,%1,%2,%3}, [%4];" \
        : "=r"((r)[0]), "=r"((r)[1]), "=r"((r)[2]), "=r"((r)[3]) : "r"(addr))
#define LDM_X2T(r, addr) \
    asm volatile("ldmatrix.sync.aligned.m8n8.x2.trans.shared.b16 {%0,%1}, [%2];" \
        : "=r"((r)[0]), "=r"((r)[1]) : "r"(addr))

__device__ __forceinline__ void mma16816(float* d, const uint32_t* a, const uint32_t* b) {
    asm volatile(
        "mma.sync.aligned.m16n8k16.row.col.f32.bf16.bf16.f32 "
        "{%0,%1,%2,%3}, {%4,%5,%6,%7}, {%8,%9}, {%0,%1,%2,%3};"
        : "+f"(d[0]), "+f"(d[1]), "+f"(d[2]), "+f"(d[3])
        : "r"(a[0]), "r"(a[1]), "r"(a[2]), "r"(a[3]), "r"(b[0]), "r"(b[1]));
}

// ---------------------------------------------------------------------------
// bf16 split GEMM: C[M,N] = A[M,K] * B[K,N].  A row-major [M][192] (hi/lo),
// B natural [K=192][N=HW] (hi/lo).  3 passes: Ah*Bh + Ah*Bl + Al*Bh.
// ---------------------------------------------------------------------------
__global__ __launch_bounds__(256, 1) void gemm_mma(
    const __nv_bfloat16* __restrict__ Ah, const __nv_bfloat16* __restrict__ Al,
    const __nv_bfloat16* __restrict__ Bh, const __nv_bfloat16* __restrict__ Bl,
    float* __restrict__ C, int Mvalid, long aBatch, long cBatch)
{
    extern __shared__ char smem[];
    const uint32_t sb = smem_u32(smem);

    const int tid  = threadIdx.x;
    const int wid  = tid >> 5;
    const int lane = tid & 31;
    const int wm   = wid >> 2;       // 0..1  (64 rows)
    const int wn   = wid & 3;        // 0..3  (32 cols)

    const int bz = blockIdx.z;
    const int m0 = blockIdx.x * BM;
    const int n0 = blockIdx.y * BN;

    Ah += (long)bz * aBatch;  Al += (long)bz * aBatch;
    Bh += (long)bz * KDIM * HW_;  Bl += (long)bz * KDIM * HW_;
    C  += (long)bz * cBatch;

    float acc[4][4][4];
    #pragma unroll
    for (int i = 0; i < 4; i++)
        #pragma unroll
        for (int j = 0; j < 4; j++)
            #pragma unroll
            for (int r = 0; r < 4; r++) acc[i][j][r] = 0.f;

    auto loadTiles = [&](int it, int buf) {
        const int pass = it / 6;
        const int k0   = (it % 6) * BK;
        const __nv_bfloat16* As = (pass == 2) ? Al : Ah;
        const __nv_bfloat16* Bs = (pass == 1) ? Bl : Bh;
        const uint32_t abase = sb + (uint32_t)buf * BUFSZ;
        const uint32_t bbase = abase + ATILE;
        #pragma unroll
        for (int i = 0; i < 2; i++) {
            const int ca = tid + 256 * i;          // A: 512 chunks of 16B
            const int ar = ca >> 2, as_ = ca & 3;
            CP_ASYNC16(abase + ar * APITCH + as_ * 16,
                       As + (long)(m0 + ar) * KDIM + k0 + as_ * 8);
            const int cb = tid + 256 * i;          // B: 512 chunks of 16B
            const int br = cb >> 4, bs_ = cb & 15;
            CP_ASYNC16(bbase + br * BPITCH + bs_ * 16,
                       Bs + (long)(k0 + br) * HW_ + n0 + bs_ * 8);
        }
    };

    loadTiles(0, 0);
    CP_COMMIT();

    #pragma unroll 1
    for (int it = 0; it < NITER; it++) {
        if (it + 1 < NITER) {
            loadTiles(it + 1, (it + 1) & 1);
            CP_COMMIT();
            CP_WAIT(1);
        } else {
            CP_WAIT(0);
        }
        __syncthreads();

        const uint32_t abase = sb + (uint32_t)(it & 1) * BUFSZ;
        const uint32_t bbase = abase + ATILE;

        #pragma unroll
        for (int kf = 0; kf < 2; kf++) {
            uint32_t a[4][4], b[4][2];
            #pragma unroll
            for (int i = 0; i < 4; i++) {
                uint32_t addr = abase
                    + (uint32_t)(wm * 64 + i * 16 + (lane & 15)) * APITCH
                    + kf * 32 + ((lane >> 4) << 4);
                LDM_X4(a[i], addr);
            }
            #pragma unroll
            for (int j = 0; j < 4; j++) {
                uint32_t addr = bbase
                    + (uint32_t)(kf * 16 + (lane & 15)) * BPITCH
                    + (uint32_t)(wn * 32 + j * 8) * 2;
                LDM_X2T(b[j], addr);
            }
            #pragma unroll
            for (int i = 0; i < 4; i++)
                #pragma unroll
                for (int j = 0; j < 4; j++)
                    mma16816(acc[i][j], a[i], b[j]);
        }
        __syncthreads();
    }

    const int rw = m0 + wm * 64 + (lane >> 2);
    const int cw = n0 + wn * 32 + (lane & 3) * 2;
    #pragma unroll
    for (int i = 0; i < 4; i++) {
        #pragma unroll
        for (int j = 0; j < 4; j++) {
            const int row = rw + i * 16;
            const int col = cw + j * 8;
            if (row < Mvalid)
                *reinterpret_cast<float2*>(C + (long)row * HW_ + col) =
                    make_float2(acc[i][j][0], acc[i][j][1]);
            if (row + 8 < Mvalid)
                *reinterpret_cast<float2*>(C + (long)(row + 8) * HW_ + col) =
                    make_float2(acc[i][j][2], acc[i][j][3]);
        }
    }
}

// ---------------------------------------------------------------------------
// 4-pixel depthwise conv helper: rows y-1..y+1, x0..x0+3 (x0 % 4 == 0, x0 < 256)
// ---------------------------------------------------------------------------
__device__ __forceinline__ void conv4(
    const float* __restrict__ plane, const float* __restrict__ w,
    int y, int x0, float out[4])
{
    out[0] = out[1] = out[2] = out[3] = 0.f;
    #pragma unroll
    for (int dy = -1; dy <= 1; dy++) {
        const int yy = y + dy;
        if (yy < 0 || yy >= HH_) continue;
        const float* row = plane + yy * WW_ + x0;
        const float4 m = *reinterpret_cast<const float4*>(row);
        const float lft = (x0 > 0)       ? row[-1] : 0.f;
        const float rgt = (x0 + 4 < 256) ? row[4]  : 0.f;
        const float w0 = w[(dy + 1) * 3 + 0];
        const float w1 = w[(dy + 1) * 3 + 1];
        const float w2 = w[(dy + 1) * 3 + 2];
        out[0] += w0 * lft + w1 * m.x + w2 * m.y;
        out[1] += w0 * m.x + w1 * m.y + w2 * m.z;
        out[2] += w0 * m.y + w1 * m.z + w2 * m.w;
        out[3] += w0 * m.z + w1 * m.w + w2 * rgt;
    }
}

// ---------------------------------------------------------------------------
// Fused depthwise conv (q,k channels) + Gram partials + sum-squares.
// grid = (GR_CHUNKS, BATCH*NHEADS), 1024 threads, dyn smem = DG_SMEM.
// Each block: one (b,h), 8 image rows. No dw tensor is ever materialized.
// ---------------------------------------------------------------------------
__global__ __launch_bounds__(1024) void dwgram(
    const float* __restrict__ qkv, const float* __restrict__ wdw)
{
    extern __shared__ float sm[];
    float* qs = sm;                  // [32][258]
    float* ks = sm + 32 * 258;       // [32][258]

    const int bh = blockIdx.y;
    const int b = bh / NHEADS, h = bh % NHEADS;
    const int chunk = blockIdx.x;
    const int tid = threadIdx.x;

    // conv task mapping
    const int ch6 = tid >> 4;        // 0..63: <32 => q, else k
    const int grp = tid & 15;
    const int c   = ch6 & 31;
    const int gch = (ch6 < 32) ? (h * HD + c) : (C_ + h * HD + c);
    const float* plane = qkv + ((long)b * C3 + gch) * HW_;
    float w[9];
    #pragma unroll
    for (int i = 0; i < 9; i++) w[i] = wdw[gch * 9 + i];
    float* dst = (ch6 < 32 ? qs : ks) + c * 258;

    // gram mapping
    const int d = tid >> 5, e = tid & 31;
    const float2* qrow = reinterpret_cast<const float2*>(qs + d * 258);
    const float2* krow = reinterpret_cast<const float2*>(ks + e * 258);

    float acc = 0.f, qsq = 0.f, ksq = 0.f;

    #pragma unroll 1
    for (int r = 0; r < 8; r++) {
        const int y = chunk * 8 + r;
        __syncthreads();
        #pragma unroll
        for (int i = 0; i < 4; i++) {
            const int x0 = (grp + 16 * i) * 4;
            float o[4];
            conv4(plane, w, y, x0, o);
            dst[x0 + 0] = o[0];  dst[x0 + 1] = o[1];
            dst[x0 + 2] = o[2];  dst[x0 + 3] = o[3];
        }
        __syncthreads();

        #pragma unroll 8
        for (int n2 = 0; n2 < 128; n2++) {
            const float2 a = qrow[n2];
            const float2 bb = krow[n2];
            acc += a.x * bb.x;
            acc += a.y * bb.y;
        }
        #pragma unroll
        for (int j = 0; j < 8; j++) {
            const float qv = qs[d * 258 + e + 32 * j];  qsq += qv * qv;
            const float kv = ks[d * 258 + e + 32 * j];  ksq += kv * kv;
        }
    }

    g_gram_part[(long)chunk * (BATCH*NHEADS*HD*HD) + bh * 1024 + d * 32 + e] = acc;
    #pragma unroll
    for (int o = 16; o > 0; o >>= 1) {
        qsq += __shfl_xor_sync(0xffffffffu, qsq, o);
        ksq += __shfl_xor_sync(0xffffffffu, ksq, o);
    }
    if (e == 0) {
        g_qsq_part[chunk * (BATCH*NHEADS*HD) + bh * HD + d] = qsq;
        g_ksq_part[chunk * (BATCH*NHEADS*HD) + bh * HD + d] = ksq;
    }
}

// ---------------------------------------------------------------------------
// Depthwise conv for v channels -> split bf16 hi/lo in [b][ch][px] layout.
// One thread handles 4 consecutive pixels.
// ---------------------------------------------------------------------------
__global__ __launch_bounds__(256) void dwv(
    const float* __restrict__ qkv, const float* __restrict__ wdw)
{
    const long idx = (long)blockIdx.x * 256 + threadIdx.x;   // < 2*192*16384
    const int px0   = (int)(idx & 16383) << 2;               // global pixel idx
    const int plane = (int)(idx >> 14);                      // b*192 + ch
    const int ch = plane % KDIM, b = plane / KDIM;
    const int gch = 2 * C_ + ch;

    const float* in = qkv + ((long)b * C3 + gch) * HW_;
    float w[9];
    #pragma unroll
    for (int i = 0; i < 9; i++) w[i] = wdw[gch * 9 + i];

    const int y  = px0 >> 8;     // pixel row
    const int x0 = px0 & 255;    // x within row (multiple of 4)
    float o[4];
    conv4(in, w, y, x0, o);

    const long off = (long)plane * HW_ + px0;
    const __nv_bfloat16 h0 = __float2bfloat16(o[0]);
    const __nv_bfloat16 h1 = __float2bfloat16(o[1]);
    const __nv_bfloat16 h2 = __float2bfloat16(o[2]);
    const __nv_bfloat16 h3 = __float2bfloat16(o[3]);
    *reinterpret_cast<__nv_bfloat162*>(g_v_h + off)     = __nv_bfloat162(h0, h1);
    *reinterpret_cast<__nv_bfloat162*>(g_v_h + off + 2) = __nv_bfloat162(h2, h3);
    *reinterpret_cast<__nv_bfloat162*>(g_v_l + off) =
        __nv_bfloat162(__float2bfloat16(o[0] - __bfloat162float(h0)),
                       __float2bfloat16(o[1] - __bfloat162float(h1)));
    *reinterpret_cast<__nv_bfloat162*>(g_v_l + off + 2) =
        __nv_bfloat162(__float2bfloat16(o[2] - __bfloat162float(h2)),
                       __float2bfloat16(o[3] - __bfloat162float(h3)));
}

// split x (fp32 [b][192][HW]) -> hi/lo bf16, same layout
__global__ __launch_bounds__(256) void split_x(const float* __restrict__ x)
{
    const long idx = (long)blockIdx.x * 256 + threadIdx.x;   // float4 groups
    const long off = idx * 4;
    const float4 f = *reinterpret_cast<const float4*>(x + off);
    const __nv_bfloat16 h0 = __float2bfloat16(f.x);
    const __nv_bfloat16 h1 = __float2bfloat16(f.y);
    const __nv_bfloat16 h2 = __float2bfloat16(f.z);
    const __nv_bfloat16 h3 = __float2bfloat16(f.w);
    *reinterpret_cast<__nv_bfloat162*>(g_x_h + off)     = __nv_bfloat162(h0, h1);
    *reinterpret_cast<__nv_bfloat162*>(g_x_h + off + 2) = __nv_bfloat162(h2, h3);
    *reinterpret_cast<__nv_bfloat162*>(g_x_l + off) =
        __nv_bfloat162(__float2bfloat16(f.x - __bfloat162float(h0)),
                       __float2bfloat16(f.y - __bfloat162float(h1)));
    *reinterpret_cast<__nv_bfloat162*>(g_x_l + off + 2) =
        __nv_bfloat162(__float2bfloat16(f.z - __bfloat162float(h2)),
                       __float2bfloat16(f.w - __bfloat162float(h3)));
}

// split w_qkv (576x192 fp32) -> A1 hi/lo (padded 640x192)
__global__ __launch_bounds__(256) void split_w1(const float* __restrict__ w)
{
    const int i = blockIdx.x * 256 + threadIdx.x;
    const float f = w[i];
    const __nv_bfloat16 h = __float2bfloat16(f);
    g_A1_h[i] = h;
    g_A1_l[i] = __float2bfloat16(f - __bfloat162float(h));
}

// reduce + normalize + temperature + softmax
__global__ __launch_bounds__(1024) void attn_kernel(const float* __restrict__ temperature)
{
    const int bh = blockIdx.x;
    const int h = bh % NHEADS;
    const int e = threadIdx.x, d = threadIdx.y;

    float g = 0.f, qsq = 0.f, ksq = 0.f;
    #pragma unroll
    for (int ch = 0; ch < GR_CHUNKS; ch++) {
        g   += g_gram_part[(long)ch * (BATCH*NHEADS*HD*HD) + bh * 1024 + d * 32 + e];
        qsq += g_qsq_part[ch * (BATCH*NHEADS*HD) + bh * HD + d];
        ksq += g_ksq_part[ch * (BATCH*NHEADS*HD) + bh * HD + e];
    }
    const float t  = fminf(temperature[h], 5.0f);
    const float qn = fmaxf(sqrtf(qsq), 1e-12f);
    const float kn = fmaxf(sqrtf(ksq), 1e-12f);
    const float val = g / (qn * kn) * t;

    float m = val;
    #pragma unroll
    for (int o = 16; o > 0; o >>= 1) m = fmaxf(m, __shfl_xor_sync(0xffffffffu, m, o));
    const float p = expf(val - m);
    float s = p;
    #pragma unroll
    for (int o = 16; o > 0; o >>= 1) s += __shfl_xor_sync(0xffffffffu, s, o);

    g_attn[bh * 1024 + d * 32 + e] = p / s;
}

// M_eff = w_proj @ blockdiag(attn) -> pre-split bf16 A2 (padded 256x192/batch)
__global__ __launch_bounds__(256) void meff_kernel(const float* __restrict__ wproj)
{
    const int idx = blockIdx.x * 256 + threadIdx.x;
    const int bz  = blockIdx.y;
    const int o   = idx / C_;
    const int ce  = idx % C_;
    const int h   = ce >> 5, e = ce & 31;

    const float* ar = g_attn + (bz * NHEADS + h) * 1024 + e;
    const float* wr = wproj + o * C_ + h * 32;

    float s = 0.f;
    #pragma unroll
    for (int dd = 0; dd < 32; dd++) s += wr[dd] * ar[dd * 32];

    const __nv_bfloat16 hi = __float2bfloat16(s);
    const long oidx = (long)bz * M2PAD * KDIM + (long)o * KDIM + ce;
    g_A2_h[oidx] = hi;
    g_A2_l[oidx] = __float2bfloat16(s - __bfloat162float(hi));
}

// ---------------------------------------------------------------------------
extern "C" void kernel_launch(void* const* d_in, const int* in_sizes, int n_in,
                              void* d_out, int out_size)
{
    (void)in_sizes; (void)n_in; (void)out_size;
    const float* x      = (const float*)d_in[0];
    const float* w_qkv  = (const float*)d_in[1];
    const float* w_dw   = (const float*)d_in[2];
    const float* w_proj = (const float*)d_in[3];
    const float* temp   = (const float*)d_in[4];
    float* out = (float*)d_out;

    float *qkv;
    __nv_bfloat16 *xh, *xl, *vh, *vl, *a1h, *a1l, *a2h, *a2l;
    cudaGetSymbolAddress((void**)&qkv, g_qkv);
    cudaGetSymbolAddress((void**)&xh, g_x_h);
    cudaGetSymbolAddress((void**)&xl, g_x_l);
    cudaGetSymbolAddress((void**)&vh, g_v_h);
    cudaGetSymbolAddress((void**)&vl, g_v_l);
    cudaGetSymbolAddress((void**)&a1h, g_A1_h);
    cudaGetSymbolAddress((void**)&a1l, g_A1_l);
    cudaGetSymbolAddress((void**)&a2h, g_A2_h);
    cudaGetSymbolAddress((void**)&a2l, g_A2_l);

    static bool attr_set = false;
    if (!attr_set) {
        cudaFuncSetAttribute(gemm_mma, cudaFuncAttributeMaxDynamicSharedMemorySize, GSMEM);
        cudaFuncSetAttribute(dwgram,   cudaFuncAttributeMaxDynamicSharedMemorySize, DG_SMEM);
        attr_set = true;
    }

    // 0) split weights + x (no transposes anywhere)
    split_w1<<<(M1 * KDIM) / 256, 256>>>(w_qkv);
    split_x<<<(int)(((long)BATCH * KDIM * HW_ / 4) / 256), 256>>>(x);

    // 1) qkv = w_qkv @ x
    gemm_mma<<<dim3(M1PAD / BM, HW_ / BN, BATCH), 256, GSMEM>>>(
        a1h, a1l, xh, xl, qkv, M1, 0L, (long)C3 * HW_);

    // 2) fused depthwise conv + gram partials (q,k) — no dw tensor
    dwgram<<<dim3(GR_CHUNKS, BATCH * NHEADS), 1024, DG_SMEM>>>(qkv, w_dw);

    // 3) depthwise conv v -> split bf16 [K][N]
    dwv<<<(int)(((long)BATCH * KDIM * HW_ / 4) / 256), 256>>>(qkv, w_dw);

    // 4) softmax + proj-absorb
    attn_kernel<<<BATCH * NHEADS, dim3(32, 32)>>>(temp);
    meff_kernel<<<dim3((C_ * C_) / 256, BATCH), 256>>>(w_proj);

    // 5) out = M_eff @ v
    gemm_mma<<<dim3(M2PAD / BM, HW_ / BN, BATCH), 256, GSMEM>>>(
        a2h, a2l, vh, vl, out, M2, (long)M2PAD * KDIM, (long)C_ * HW_);
}

// round 6
// speedup vs baseline: 1.9867x; 1.2867x over previous
#include <cuda_runtime.h>
#include <cuda_bf16.h>
#include <cstdint>

#define C_     192
#define C3     576
#define NHEADS 6
#define HD     32
#define HH_    256
#define WW_    256
#define HW_    65536
#define BATCH  2
#define KDIM   192
#define M1     576
#define M1PAD  640
#define M2     192
#define M2PAD  256

#define GR_CHUNKS 32           // 32 chunks x 8 rows = 256 image rows

// GEMM tiling (single pass: Ah,Al,Bh,Bl all resident per k-tile)
#define BM 128
#define BN 128
#define BK 32
#define APITCH 80              // bytes per A smem row (64B data + 16B pad)
#define BPITCH 272             // bytes per B smem row (256B data + 16B pad)
#define ATILE (BM * APITCH)    // 10240
#define BTILE (BK * BPITCH)    // 8704
#define BUFSZ (2 * ATILE + 2 * BTILE)  // 37888
#define GSMEM (2 * BUFSZ)              // 75776
#define NITER 6                        // 192/32 k-tiles, one pass

#define GP 261                         // dwgram smem pitch (mod 32 = 5)
#define DG_SMEM (2 * 32 * GP * 4)      // 66816 B

// ---------------- scratch (device globals) -----------------------------------
__device__ float g_qkv[BATCH * C3 * HW_];
__device__ __nv_bfloat16 g_x_h[BATCH * KDIM * HW_];   // [b][k][n]
__device__ __nv_bfloat16 g_x_l[BATCH * KDIM * HW_];
__device__ __nv_bfloat16 g_v_h[BATCH * KDIM * HW_];
__device__ __nv_bfloat16 g_v_l[BATCH * KDIM * HW_];
__device__ __nv_bfloat16 g_A1_h[M1PAD * KDIM];        // padded rows stay zero
__device__ __nv_bfloat16 g_A1_l[M1PAD * KDIM];
__device__ __nv_bfloat16 g_A2_h[BATCH * M2PAD * KDIM];
__device__ __nv_bfloat16 g_A2_l[BATCH * M2PAD * KDIM];
__device__ float g_gram_part[GR_CHUNKS * BATCH * NHEADS * HD * HD];
__device__ float g_qsq_part [GR_CHUNKS * BATCH * NHEADS * HD];
__device__ float g_ksq_part [GR_CHUNKS * BATCH * NHEADS * HD];
__device__ float g_attn[BATCH * NHEADS * HD * HD];

// ---------------- PTX helpers (sm_80+ only) ----------------------------------
__device__ __forceinline__ uint32_t smem_u32(const void* p) {
    uint32_t a;
    asm("{ .reg .u64 t; cvta.to.shared.u64 t, %1; cvt.u32.u64 %0, t; }" : "=r"(a) : "l"(p));
    return a;
}
#define CP_ASYNC16(dst, src) \
    asm volatile("cp.async.cg.shared.global [%0], [%1], 16;" :: "r"(dst), "l"(src))
#define CP_COMMIT() asm volatile("cp.async.commit_group;" ::: "memory")
#define CP_WAIT(n)  asm volatile("cp.async.wait_group %0;" :: "n"(n) : "memory")

#define LDM_X4(r, addr) \
    asm volatile("ldmatrix.sync.aligned.m8n8.x4.shared.b16 {%0,%1,%2,%3}, [%4];" \
        : "=r"((r)[0]), "=r"((r)[1]), "=r"((r)[2]), "=r"((r)[3]) : "r"(addr))
#define LDM_X2T(r, addr) \
    asm volatile("ldmatrix.sync.aligned.m8n8.x2.trans.shared.b16 {%0,%1}, [%2];" \
        : "=r"((r)[0]), "=r"((r)[1]) : "r"(addr))

__device__ __forceinline__ void mma16816(float* d, const uint32_t* a, const uint32_t* b) {
    asm volatile(
        "mma.sync.aligned.m16n8k16.row.col.f32.bf16.bf16.f32 "
        "{%0,%1,%2,%3}, {%4,%5,%6,%7}, {%8,%9}, {%0,%1,%2,%3};"
        : "+f"(d[0]), "+f"(d[1]), "+f"(d[2]), "+f"(d[3])
        : "r"(a[0]), "r"(a[1]), "r"(a[2]), "r"(a[3]), "r"(b[0]), "r"(b[1]));
}

// ---------------------------------------------------------------------------
// Single-pass split-bf16 GEMM: C = A*B, A[M][192] hi/lo, B[192][HW] hi/lo.
// Per k-tile all 4 tiles resident; 3 products accumulated: AhBh + AhBl + AlBh.
// ---------------------------------------------------------------------------
__global__ __launch_bounds__(256, 1) void gemm_mma(
    const __nv_bfloat16* __restrict__ Ah, const __nv_bfloat16* __restrict__ Al,
    const __nv_bfloat16* __restrict__ Bh, const __nv_bfloat16* __restrict__ Bl,
    float* __restrict__ C, int Mvalid, long aBatch, long cBatch)
{
    extern __shared__ char smem[];
    const uint32_t sb = smem_u32(smem);

    const int tid  = threadIdx.x;
    const int wid  = tid >> 5;
    const int lane = tid & 31;
    const int wm   = wid >> 2;       // 0..1  (64 rows)
    const int wn   = wid & 3;        // 0..3  (32 cols)

    const int bz = blockIdx.z;
    const int m0 = blockIdx.x * BM;
    const int n0 = blockIdx.y * BN;

    Ah += (long)bz * aBatch;  Al += (long)bz * aBatch;
    Bh += (long)bz * KDIM * HW_;  Bl += (long)bz * KDIM * HW_;
    C  += (long)bz * cBatch;

    float acc[4][4][4];
    #pragma unroll
    for (int i = 0; i < 4; i++)
        #pragma unroll
        for (int j = 0; j < 4; j++)
            #pragma unroll
            for (int r = 0; r < 4; r++) acc[i][j][r] = 0.f;

    auto loadTiles = [&](int it, int buf) {
        const int k0 = it * BK;
        const uint32_t base = sb + (uint32_t)buf * BUFSZ;
        #pragma unroll
        for (int i = 0; i < 2; i++) {
            const int ca = tid + 256 * i;          // 0..511
            const int ar = ca >> 2, as_ = ca & 3;
            const long goff = (long)(m0 + ar) * KDIM + k0 + as_ * 8;
            const uint32_t soff = ar * APITCH + as_ * 16;
            CP_ASYNC16(base + soff,          Ah + goff);
            CP_ASYNC16(base + ATILE + soff,  Al + goff);
            const int br = ca >> 4, bs_ = ca & 15;
            const long gob = (long)(k0 + br) * HW_ + n0 + bs_ * 8;
            const uint32_t sofb = br * BPITCH + bs_ * 16;
            CP_ASYNC16(base + 2 * ATILE + sofb,         Bh + gob);
            CP_ASYNC16(base + 2 * ATILE + BTILE + sofb, Bl + gob);
        }
    };

    loadTiles(0, 0);
    CP_COMMIT();

    #pragma unroll 1
    for (int it = 0; it < NITER; it++) {
        if (it + 1 < NITER) {
            loadTiles(it + 1, (it + 1) & 1);
            CP_COMMIT();
            CP_WAIT(1);
        } else {
            CP_WAIT(0);
        }
        __syncthreads();

        const uint32_t base  = sb + (uint32_t)(it & 1) * BUFSZ;
        const uint32_t aHb = base, aLb = base + ATILE;
        const uint32_t bHb = base + 2 * ATILE, bLb = bHb + BTILE;

        #pragma unroll
        for (int kf = 0; kf < 2; kf++) {
            uint32_t aH[4][4], aL[4][4], bH[4][2], bL[4][2];
            #pragma unroll
            for (int i = 0; i < 4; i++) {
                const uint32_t ro = (uint32_t)(wm * 64 + i * 16 + (lane & 15)) * APITCH
                                  + kf * 32 + ((lane >> 4) << 4);
                LDM_X4(aH[i], aHb + ro);
                LDM_X4(aL[i], aLb + ro);
            }
            #pragma unroll
            for (int j = 0; j < 4; j++) {
                const uint32_t ro = (uint32_t)(kf * 16 + (lane & 15)) * BPITCH
                                  + (uint32_t)(wn * 32 + j * 8) * 2;
                LDM_X2T(bH[j], bHb + ro);
                LDM_X2T(bL[j], bLb + ro);
            }
            #pragma unroll
            for (int i = 0; i < 4; i++)
                #pragma unroll
                for (int j = 0; j < 4; j++) {
                    mma16816(acc[i][j], aH[i], bH[j]);
                    mma16816(acc[i][j], aH[i], bL[j]);
                    mma16816(acc[i][j], aL[i], bH[j]);
                }
        }
        __syncthreads();
    }

    const int rw = m0 + wm * 64 + (lane >> 2);
    const int cw = n0 + wn * 32 + (lane & 3) * 2;
    #pragma unroll
    for (int i = 0; i < 4; i++) {
        #pragma unroll
        for (int j = 0; j < 4; j++) {
            const int row = rw + i * 16;
            const int col = cw + j * 8;
            if (row < Mvalid)
                *reinterpret_cast<float2*>(C + (long)row * HW_ + col) =
                    make_float2(acc[i][j][0], acc[i][j][1]);
            if (row + 8 < Mvalid)
                *reinterpret_cast<float2*>(C + (long)(row + 8) * HW_ + col) =
                    make_float2(acc[i][j][2], acc[i][j][3]);
        }
    }
}

// ---------------------------------------------------------------------------
// 4-pixel depthwise conv: rows y-1..y+1, x0..x0+3 (x0 % 4 == 0, x0 in [0,256))
// ---------------------------------------------------------------------------
__device__ __forceinline__ void conv4(
    const float* __restrict__ plane, const float* __restrict__ w,
    int y, int x0, float out[4])
{
    out[0] = out[1] = out[2] = out[3] = 0.f;
    #pragma unroll
    for (int dy = -1; dy <= 1; dy++) {
        const int yy = y + dy;
        if (yy < 0 || yy >= HH_) continue;
        const float* row = plane + yy * WW_ + x0;
        const float4 m = *reinterpret_cast<const float4*>(row);
        const float lft = (x0 > 0)       ? row[-1] : 0.f;
        const float rgt = (x0 + 4 < 256) ? row[4]  : 0.f;
        const float w0 = w[(dy + 1) * 3 + 0];
        const float w1 = w[(dy + 1) * 3 + 1];
        const float w2 = w[(dy + 1) * 3 + 2];
        out[0] += w0 * lft + w1 * m.x + w2 * m.y;
        out[1] += w0 * m.x + w1 * m.y + w2 * m.z;
        out[2] += w0 * m.y + w1 * m.z + w2 * m.w;
        out[3] += w0 * m.z + w1 * m.w + w2 * rgt;
    }
}

// ---------------------------------------------------------------------------
// Fused depthwise conv (q,k) + register-tiled Gram partials + sum-squares.
// grid = (GR_CHUNKS, BATCH*NHEADS), 512 threads, dyn smem = DG_SMEM.
// Gram: 8 groups x 64 threads; each thread owns a 4x4 tile of G over a
// 32-pixel slice of each image row (16 FMA / 8 LDS).
// ---------------------------------------------------------------------------
__global__ __launch_bounds__(512) void dwgram(
    const float* __restrict__ qkv, const float* __restrict__ wdw)
{
    extern __shared__ float sm[];
    float* qs = sm;                  // [32][GP]
    float* ks = sm + 32 * GP;        // [32][GP]

    const int bh = blockIdx.y;
    const int b = bh / NHEADS, h = bh % NHEADS;
    const int chunk = blockIdx.x;
    const int tid = threadIdx.x;

    // conv mapping: 64 channels x 8 x-groups
    const int ch6 = tid >> 3;        // 0..63: <32 => q, else k
    const int grp = tid & 7;
    const int c   = ch6 & 31;
    const int gch = (ch6 < 32) ? (h * HD + c) : (C_ + h * HD + c);
    const float* plane = qkv + ((long)b * C3 + gch) * HW_;
    float w[9];
    #pragma unroll
    for (int i = 0; i < 9; i++) w[i] = wdw[gch * 9 + i];
    float* dst = (ch6 < 32 ? qs : ks) + c * GP;

    // gram mapping: group g handles pixels [32g, 32g+32)
    const int g  = tid >> 6;         // 0..7
    const int ti = (tid >> 3) & 7;   // 0..7 -> rows 4ti..4ti+3
    const int tj = tid & 7;          // 0..7 -> cols 4tj..4tj+3
    const int nbase = g * 32;

    // sum-squares mapping
    const int sd  = tid >> 4;        // 0..31
    const int se  = tid & 15;        // 0..15

    float accG[4][4];
    #pragma unroll
    for (int i = 0; i < 4; i++)
        #pragma unroll
        for (int j = 0; j < 4; j++) accG[i][j] = 0.f;
    float qsq = 0.f, ksq = 0.f;

    #pragma unroll 1
    for (int r = 0; r < 8; r++) {
        const int y = chunk * 8 + r;
        __syncthreads();
        #pragma unroll
        for (int i = 0; i < 8; i++) {
            const int x0 = (grp + 8 * i) * 4;
            float o[4];
            conv4(plane, w, y, x0, o);
            dst[x0 + 0] = o[0];  dst[x0 + 1] = o[1];
            dst[x0 + 2] = o[2];  dst[x0 + 3] = o[3];
        }
        __syncthreads();

        const float* qbase = qs + 4 * ti * GP + nbase;
        const float* kbase = ks + 4 * tj * GP + nbase;
        #pragma unroll 4
        for (int n = 0; n < 32; n++) {
            float qv[4], kv[4];
            #pragma unroll
            for (int i = 0; i < 4; i++) qv[i] = qbase[i * GP + n];
            #pragma unroll
            for (int j = 0; j < 4; j++) kv[j] = kbase[j * GP + n];
            #pragma unroll
            for (int i = 0; i < 4; i++)
                #pragma unroll
                for (int j = 0; j < 4; j++)
                    accG[i][j] += qv[i] * kv[j];
        }

        #pragma unroll
        for (int j = 0; j < 16; j++) {
            const float qv = qs[sd * GP + se + 16 * j];  qsq += qv * qv;
            const float kv = ks[sd * GP + se + 16 * j];  ksq += kv * kv;
        }
    }

    // reduce gram partials across the 8 groups via smem (reuse tile area)
    __syncthreads();
    #pragma unroll
    for (int i = 0; i < 4; i++)
        #pragma unroll
        for (int j = 0; j < 4; j++)
            sm[g * 1024 + (4 * ti + i) * 32 + (4 * tj + j)] = accG[i][j];
    __syncthreads();

    #pragma unroll
    for (int o = 0; o < 2; o++) {
        const int out = tid + 512 * o;
        float s = 0.f;
        #pragma unroll
        for (int gg = 0; gg < 8; gg++) s += sm[gg * 1024 + out];
        g_gram_part[(long)chunk * (BATCH*NHEADS*HD*HD) + bh * 1024 + out] = s;
    }

    // sum-squares reduce over 16 lanes
    #pragma unroll
    for (int o = 8; o > 0; o >>= 1) {
        qsq += __shfl_xor_sync(0xffffffffu, qsq, o);
        ksq += __shfl_xor_sync(0xffffffffu, ksq, o);
    }
    if (se == 0) {
        g_qsq_part[chunk * (BATCH*NHEADS*HD) + bh * HD + sd] = qsq;
        g_ksq_part[chunk * (BATCH*NHEADS*HD) + bh * HD + sd] = ksq;
    }
}

// ---------------------------------------------------------------------------
// Depthwise conv for v channels -> split bf16 hi/lo in [b][ch][px] layout.
// ---------------------------------------------------------------------------
__global__ __launch_bounds__(256) void dwv(
    const float* __restrict__ qkv, const float* __restrict__ wdw)
{
    const long idx = (long)blockIdx.x * 256 + threadIdx.x;   // < 2*192*16384
    const int px0   = (int)(idx & 16383) << 2;
    const int plane = (int)(idx >> 14);                      // b*192 + ch
    const int ch = plane % KDIM, b = plane / KDIM;
    const int gch = 2 * C_ + ch;

    const float* in = qkv + ((long)b * C3 + gch) * HW_;
    float w[9];
    #pragma unroll
    for (int i = 0; i < 9; i++) w[i] = wdw[gch * 9 + i];

    const int y  = px0 >> 8;
    const int x0 = px0 & 255;
    float o[4];
    conv4(in, w, y, x0, o);

    const long off = (long)plane * HW_ + px0;
    const __nv_bfloat16 h0 = __float2bfloat16(o[0]);
    const __nv_bfloat16 h1 = __float2bfloat16(o[1]);
    const __nv_bfloat16 h2 = __float2bfloat16(o[2]);
    const __nv_bfloat16 h3 = __float2bfloat16(o[3]);
    *reinterpret_cast<__nv_bfloat162*>(g_v_h + off)     = __nv_bfloat162(h0, h1);
    *reinterpret_cast<__nv_bfloat162*>(g_v_h + off + 2) = __nv_bfloat162(h2, h3);
    *reinterpret_cast<__nv_bfloat162*>(g_v_l + off) =
        __nv_bfloat162(__float2bfloat16(o[0] - __bfloat162float(h0)),
                       __float2bfloat16(o[1] - __bfloat162float(h1)));
    *reinterpret_cast<__nv_bfloat162*>(g_v_l + off + 2) =
        __nv_bfloat162(__float2bfloat16(o[2] - __bfloat162float(h2)),
                       __float2bfloat16(o[3] - __bfloat162float(h3)));
}

// split x (fp32 [b][192][HW]) -> hi/lo bf16, same layout
__global__ __launch_bounds__(256) void split_x(const float* __restrict__ x)
{
    const long idx = (long)blockIdx.x * 256 + threadIdx.x;
    const long off = idx * 4;
    const float4 f = *reinterpret_cast<const float4*>(x + off);
    const __nv_bfloat16 h0 = __float2bfloat16(f.x);
    const __nv_bfloat16 h1 = __float2bfloat16(f.y);
    const __nv_bfloat16 h2 = __float2bfloat16(f.z);
    const __nv_bfloat16 h3 = __float2bfloat16(f.w);
    *reinterpret_cast<__nv_bfloat162*>(g_x_h + off)     = __nv_bfloat162(h0, h1);
    *reinterpret_cast<__nv_bfloat162*>(g_x_h + off + 2) = __nv_bfloat162(h2, h3);
    *reinterpret_cast<__nv_bfloat162*>(g_x_l + off) =
        __nv_bfloat162(__float2bfloat16(f.x - __bfloat162float(h0)),
                       __float2bfloat16(f.y - __bfloat162float(h1)));
    *reinterpret_cast<__nv_bfloat162*>(g_x_l + off + 2) =
        __nv_bfloat162(__float2bfloat16(f.z - __bfloat162float(h2)),
                       __float2bfloat16(f.w - __bfloat162float(h3)));
}

// split w_qkv (576x192 fp32) -> A1 hi/lo (padded 640x192)
__global__ __launch_bounds__(256) void split_w1(const float* __restrict__ w)
{
    const int i = blockIdx.x * 256 + threadIdx.x;
    const float f = w[i];
    const __nv_bfloat16 h = __float2bfloat16(f);
    g_A1_h[i] = h;
    g_A1_l[i] = __float2bfloat16(f - __bfloat162float(h));
}

// reduce + normalize + temperature + softmax
__global__ __launch_bounds__(1024) void attn_kernel(const float* __restrict__ temperature)
{
    const int bh = blockIdx.x;
    const int h = bh % NHEADS;
    const int e = threadIdx.x, d = threadIdx.y;

    float g = 0.f, qsq = 0.f, ksq = 0.f;
    #pragma unroll
    for (int ch = 0; ch < GR_CHUNKS; ch++) {
        g   += g_gram_part[(long)ch * (BATCH*NHEADS*HD*HD) + bh * 1024 + d * 32 + e];
        qsq += g_qsq_part[ch * (BATCH*NHEADS*HD) + bh * HD + d];
        ksq += g_ksq_part[ch * (BATCH*NHEADS*HD) + bh * HD + e];
    }
    const float t  = fminf(temperature[h], 5.0f);
    const float qn = fmaxf(sqrtf(qsq), 1e-12f);
    const float kn = fmaxf(sqrtf(ksq), 1e-12f);
    const float val = g / (qn * kn) * t;

    float m = val;
    #pragma unroll
    for (int o = 16; o > 0; o >>= 1) m = fmaxf(m, __shfl_xor_sync(0xffffffffu, m, o));
    const float p = expf(val - m);
    float s = p;
    #pragma unroll
    for (int o = 16; o > 0; o >>= 1) s += __shfl_xor_sync(0xffffffffu, s, o);

    g_attn[bh * 1024 + d * 32 + e] = p / s;
}

// M_eff = w_proj @ blockdiag(attn) -> pre-split bf16 A2 (padded 256x192/batch)
__global__ __launch_bounds__(256) void meff_kernel(const float* __restrict__ wproj)
{
    const int idx = blockIdx.x * 256 + threadIdx.x;
    const int bz  = blockIdx.y;
    const int o   = idx / C_;
    const int ce  = idx % C_;
    const int h   = ce >> 5, e = ce & 31;

    const float* ar = g_attn + (bz * NHEADS + h) * 1024 + e;
    const float* wr = wproj + o * C_ + h * 32;

    float s = 0.f;
    #pragma unroll
    for (int dd = 0; dd < 32; dd++) s += wr[dd] * ar[dd * 32];

    const __nv_bfloat16 hi = __float2bfloat16(s);
    const long oidx = (long)bz * M2PAD * KDIM + (long)o * KDIM + ce;
    g_A2_h[oidx] = hi;
    g_A2_l[oidx] = __float2bfloat16(s - __bfloat162float(hi));
}

// ---------------------------------------------------------------------------
extern "C" void kernel_launch(void* const* d_in, const int* in_sizes, int n_in,
                              void* d_out, int out_size)
{
    (void)in_sizes; (void)n_in; (void)out_size;
    const float* x      = (const float*)d_in[0];
    const float* w_qkv  = (const float*)d_in[1];
    const float* w_dw   = (const float*)d_in[2];
    const float* w_proj = (const float*)d_in[3];
    const float* temp   = (const float*)d_in[4];
    float* out = (float*)d_out;

    float *qkv;
    __nv_bfloat16 *xh, *xl, *vh, *vl, *a1h, *a1l, *a2h, *a2l;
    cudaGetSymbolAddress((void**)&qkv, g_qkv);
    cudaGetSymbolAddress((void**)&xh, g_x_h);
    cudaGetSymbolAddress((void**)&xl, g_x_l);
    cudaGetSymbolAddress((void**)&vh, g_v_h);
    cudaGetSymbolAddress((void**)&vl, g_v_l);
    cudaGetSymbolAddress((void**)&a1h, g_A1_h);
    cudaGetSymbolAddress((void**)&a1l, g_A1_l);
    cudaGetSymbolAddress((void**)&a2h, g_A2_h);
    cudaGetSymbolAddress((void**)&a2l, g_A2_l);

    static bool attr_set = false;
    if (!attr_set) {
        cudaFuncSetAttribute(gemm_mma, cudaFuncAttributeMaxDynamicSharedMemorySize, GSMEM);
        cudaFuncSetAttribute(dwgram,   cudaFuncAttributeMaxDynamicSharedMemorySize, DG_SMEM);
        attr_set = true;
    }

    // 0) split weights + x
    split_w1<<<(M1 * KDIM) / 256, 256>>>(w_qkv);
    split_x<<<(int)(((long)BATCH * KDIM * HW_ / 4) / 256), 256>>>(x);

    // 1) qkv = w_qkv @ x
    gemm_mma<<<dim3(M1PAD / BM, HW_ / BN, BATCH), 256, GSMEM>>>(
        a1h, a1l, xh, xl, qkv, M1, 0L, (long)C3 * HW_);

    // 2) fused depthwise conv + gram partials (q,k)
    dwgram<<<dim3(GR_CHUNKS, BATCH * NHEADS), 512, DG_SMEM>>>(qkv, w_dw);

    // 3) depthwise conv v -> split bf16 [K][N]
    dwv<<<(int)(((long)BATCH * KDIM * HW_ / 4) / 256), 256>>>(qkv, w_dw);

    // 4) softmax + proj-absorb
    attn_kernel<<<BATCH * NHEADS, dim3(32, 32)>>>(temp);
    meff_kernel<<<dim3((C_ * C_) / 256, BATCH), 256>>>(w_proj);

    // 5) out = M_eff @ v
    gemm_mma<<<dim3(M2PAD / BM, HW_ / BN, BATCH), 256, GSMEM>>>(
        a2h, a2l, vh, vl, out, M2, (long)M2PAD * KDIM, (long)C_ * HW_);
}

// round 7
// speedup vs baseline: 2.5178x; 1.2673x over previous
#include <cuda_runtime.h>
#include <cuda_bf16.h>
#include <cstdint>

#define C_     192
#define C3     576
#define NHEADS 6
#define HD     32
#define HH_    256
#define WW_    256
#define HW_    65536
#define BATCH  2
#define KDIM   192
#define M1     576
#define M1PAD  640
#define M2     192
#define M2PAD  256

#define GR_CHUNKS 64           // 64 chunks x 4 rows = 256 image rows
#define ROWS_PC   4

// GEMM tiling (single pass: Ah,Al,Bh,Bl all resident per k-tile)
#define BM 128
#define BN 128
#define BK 32
#define APITCH 80              // bytes per A smem row (64B data + 16B pad)
#define BPITCH 272             // bytes per B smem row (256B data + 16B pad)
#define ATILE (BM * APITCH)    // 10240
#define BTILE (BK * BPITCH)    // 8704
#define BUFSZ (2 * ATILE + 2 * BTILE)  // 37888
#define GSMEM (2 * BUFSZ)              // 75776
#define NITER 6                        // 192/32 k-tiles, one pass

#define GP 261                         // dwgram smem pitch (mod 32 = 5)
#define DG_SMEM (2 * 32 * GP * 4)      // 66816 B

// ---------------- scratch (device globals) -----------------------------------
__device__ float g_qkv[BATCH * C3 * HW_];
__device__ __nv_bfloat16 g_x_h[BATCH * KDIM * HW_];   // [b][k][n]
__device__ __nv_bfloat16 g_x_l[BATCH * KDIM * HW_];
__device__ __nv_bfloat16 g_v_h[BATCH * KDIM * HW_];
__device__ __nv_bfloat16 g_v_l[BATCH * KDIM * HW_];
__device__ __nv_bfloat16 g_A1_h[M1PAD * KDIM];        // padded rows stay zero
__device__ __nv_bfloat16 g_A1_l[M1PAD * KDIM];
__device__ __nv_bfloat16 g_A2_h[BATCH * M2PAD * KDIM];
__device__ __nv_bfloat16 g_A2_l[BATCH * M2PAD * KDIM];
__device__ float g_gram_part[GR_CHUNKS * BATCH * NHEADS * HD * HD];
__device__ float g_qsq_part [GR_CHUNKS * BATCH * NHEADS * HD];
__device__ float g_ksq_part [GR_CHUNKS * BATCH * NHEADS * HD];
__device__ float g_attn[BATCH * NHEADS * HD * HD];

// ---------------- PTX helpers (sm_80+ only) ----------------------------------
__device__ __forceinline__ uint32_t smem_u32(const void* p) {
    uint32_t a;
    asm("{ .reg .u64 t; cvta.to.shared.u64 t, %1; cvt.u32.u64 %0, t; }" : "=r"(a) : "l"(p));
    return a;
}
#define CP_ASYNC16(dst, src) \
    asm volatile("cp.async.cg.shared.global [%0], [%1], 16;" :: "r"(dst), "l"(src))
#define CP_COMMIT() asm volatile("cp.async.commit_group;" ::: "memory")
#define CP_WAIT(n)  asm volatile("cp.async.wait_group %0;" :: "n"(n) : "memory")

#define LDM_X4(r, addr) \
    asm volatile("ldmatrix.sync.aligned.m8n8.x4.shared.b16 {%0,%1,%2,%3}, [%4];" \
        : "=r"((r)[0]), "=r"((r)[1]), "=r"((r)[2]), "=r"((r)[3]) : "r"(addr))
#define LDM_X2T(r, addr) \
    asm volatile("ldmatrix.sync.aligned.m8n8.x2.trans.shared.b16 {%0,%1}, [%2];" \
        : "=r"((r)[0]), "=r"((r)[1]) : "r"(addr))

__device__ __forceinline__ void mma16816(float* d, const uint32_t* a, const uint32_t* b) {
    asm volatile(
        "mma.sync.aligned.m16n8k16.row.col.f32.bf16.bf16.f32 "
        "{%0,%1,%2,%3}, {%4,%5,%6,%7}, {%8,%9}, {%0,%1,%2,%3};"
        : "+f"(d[0]), "+f"(d[1]), "+f"(d[2]), "+f"(d[3])
        : "r"(a[0]), "r"(a[1]), "r"(a[2]), "r"(a[3]), "r"(b[0]), "r"(b[1]));
}

// ---------------------------------------------------------------------------
// Single-pass split-bf16 GEMM: C = A*B, A[M][192] hi/lo, B[192][HW] hi/lo.
// ---------------------------------------------------------------------------
__global__ __launch_bounds__(256, 2) void gemm_mma(
    const __nv_bfloat16* __restrict__ Ah, const __nv_bfloat16* __restrict__ Al,
    const __nv_bfloat16* __restrict__ Bh, const __nv_bfloat16* __restrict__ Bl,
    float* __restrict__ C, int Mvalid, long aBatch, long cBatch)
{
    extern __shared__ char smem[];
    const uint32_t sb = smem_u32(smem);

    const int tid  = threadIdx.x;
    const int wid  = tid >> 5;
    const int lane = tid & 31;
    const int wm   = wid >> 2;       // 0..1  (64 rows)
    const int wn   = wid & 3;        // 0..3  (32 cols)

    const int bz = blockIdx.z;
    const int m0 = blockIdx.x * BM;
    const int n0 = blockIdx.y * BN;

    Ah += (long)bz * aBatch;  Al += (long)bz * aBatch;
    Bh += (long)bz * KDIM * HW_;  Bl += (long)bz * KDIM * HW_;
    C  += (long)bz * cBatch;

    float acc[4][4][4];
    #pragma unroll
    for (int i = 0; i < 4; i++)
        #pragma unroll
        for (int j = 0; j < 4; j++)
            #pragma unroll
            for (int r = 0; r < 4; r++) acc[i][j][r] = 0.f;

    auto loadTiles = [&](int it, int buf) {
        const int k0 = it * BK;
        const uint32_t base = sb + (uint32_t)buf * BUFSZ;
        #pragma unroll
        for (int i = 0; i < 2; i++) {
            const int ca = tid + 256 * i;          // 0..511
            const int ar = ca >> 2, as_ = ca & 3;
            const long goff = (long)(m0 + ar) * KDIM + k0 + as_ * 8;
            const uint32_t soff = ar * APITCH + as_ * 16;
            CP_ASYNC16(base + soff,          Ah + goff);
            CP_ASYNC16(base + ATILE + soff,  Al + goff);
            const int br = ca >> 4, bs_ = ca & 15;
            const long gob = (long)(k0 + br) * HW_ + n0 + bs_ * 8;
            const uint32_t sofb = br * BPITCH + bs_ * 16;
            CP_ASYNC16(base + 2 * ATILE + sofb,         Bh + gob);
            CP_ASYNC16(base + 2 * ATILE + BTILE + sofb, Bl + gob);
        }
    };

    loadTiles(0, 0);
    CP_COMMIT();

    #pragma unroll 1
    for (int it = 0; it < NITER; it++) {
        if (it + 1 < NITER) {
            loadTiles(it + 1, (it + 1) & 1);
            CP_COMMIT();
            CP_WAIT(1);
        } else {
            CP_WAIT(0);
        }
        __syncthreads();

        const uint32_t base  = sb + (uint32_t)(it & 1) * BUFSZ;
        const uint32_t aHb = base, aLb = base + ATILE;
        const uint32_t bHb = base + 2 * ATILE, bLb = bHb + BTILE;

        #pragma unroll
        for (int kf = 0; kf < 2; kf++) {
            uint32_t aH[4][4], aL[4][4], bH[4][2], bL[4][2];
            #pragma unroll
            for (int i = 0; i < 4; i++) {
                const uint32_t ro = (uint32_t)(wm * 64 + i * 16 + (lane & 15)) * APITCH
                                  + kf * 32 + ((lane >> 4) << 4);
                LDM_X4(aH[i], aHb + ro);
                LDM_X4(aL[i], aLb + ro);
            }
            #pragma unroll
            for (int j = 0; j < 4; j++) {
                const uint32_t ro = (uint32_t)(kf * 16 + (lane & 15)) * BPITCH
                                  + (uint32_t)(wn * 32 + j * 8) * 2;
                LDM_X2T(bH[j], bHb + ro);
                LDM_X2T(bL[j], bLb + ro);
            }
            #pragma unroll
            for (int i = 0; i < 4; i++)
                #pragma unroll
                for (int j = 0; j < 4; j++) {
                    mma16816(acc[i][j], aH[i], bH[j]);
                    mma16816(acc[i][j], aH[i], bL[j]);
                    mma16816(acc[i][j], aL[i], bH[j]);
                }
        }
        __syncthreads();
    }

    const int rw = m0 + wm * 64 + (lane >> 2);
    const int cw = n0 + wn * 32 + (lane & 3) * 2;
    #pragma unroll
    for (int i = 0; i < 4; i++) {
        #pragma unroll
        for (int j = 0; j < 4; j++) {
            const int row = rw + i * 16;
            const int col = cw + j * 8;
            if (row < Mvalid)
                *reinterpret_cast<float2*>(C + (long)row * HW_ + col) =
                    make_float2(acc[i][j][0], acc[i][j][1]);
            if (row + 8 < Mvalid)
                *reinterpret_cast<float2*>(C + (long)(row + 8) * HW_ + col) =
                    make_float2(acc[i][j][2], acc[i][j][3]);
        }
    }
}

// ---------------------------------------------------------------------------
// 4-pixel depthwise conv: rows y-1..y+1, x0..x0+3 (x0 % 4 == 0, x0 in [0,256))
// ---------------------------------------------------------------------------
__device__ __forceinline__ void conv4(
    const float* __restrict__ plane, const float* __restrict__ w,
    int y, int x0, float out[4])
{
    out[0] = out[1] = out[2] = out[3] = 0.f;
    #pragma unroll
    for (int dy = -1; dy <= 1; dy++) {
        const int yy = y + dy;
        if (yy < 0 || yy >= HH_) continue;
        const float* row = plane + yy * WW_ + x0;
        const float4 m = *reinterpret_cast<const float4*>(row);
        const float lft = (x0 > 0)       ? row[-1] : 0.f;
        const float rgt = (x0 + 4 < 256) ? row[4]  : 0.f;
        const float w0 = w[(dy + 1) * 3 + 0];
        const float w1 = w[(dy + 1) * 3 + 1];
        const float w2 = w[(dy + 1) * 3 + 2];
        out[0] += w0 * lft + w1 * m.x + w2 * m.y;
        out[1] += w0 * m.x + w1 * m.y + w2 * m.z;
        out[2] += w0 * m.y + w1 * m.z + w2 * m.w;
        out[3] += w0 * m.z + w1 * m.w + w2 * rgt;
    }
}

// ---------------------------------------------------------------------------
// Fused depthwise conv (q,k) + register-tiled Gram partials.
// Sum-squares accumulated IN the conv phase from register outputs (no LDS),
// reduced over the 8 x-group lanes by xor-shuffle.
// grid = (GR_CHUNKS, BATCH*NHEADS), 512 threads, 2 blocks/SM.
// ---------------------------------------------------------------------------
__global__ __launch_bounds__(512, 2) void dwgram(
    const float* __restrict__ qkv, const float* __restrict__ wdw)
{
    extern __shared__ float sm[];
    float* qs = sm;                  // [32][GP]
    float* ks = sm + 32 * GP;        // [32][GP]

    const int bh = blockIdx.y;
    const int b = bh / NHEADS, h = bh % NHEADS;
    const int chunk = blockIdx.x;
    const int tid = threadIdx.x;

    // conv mapping: 64 channels x 8 x-groups
    const int ch6 = tid >> 3;        // 0..63: <32 => q, else k
    const int grp = tid & 7;
    const int c   = ch6 & 31;
    const int gch = (ch6 < 32) ? (h * HD + c) : (C_ + h * HD + c);
    const float* plane = qkv + ((long)b * C3 + gch) * HW_;
    float w[9];
    #pragma unroll
    for (int i = 0; i < 9; i++) w[i] = wdw[gch * 9 + i];
    float* dst = (ch6 < 32 ? qs : ks) + c * GP;

    // gram mapping: group g handles pixels [32g, 32g+32)
    const int g  = tid >> 6;         // 0..7
    const int ti = (tid >> 3) & 7;   // 0..7 -> rows 4ti..4ti+3
    const int tj = tid & 7;          // 0..7 -> cols 4tj..4tj+3
    const int nbase = g * 32;

    float accG[4][4];
    #pragma unroll
    for (int i = 0; i < 4; i++)
        #pragma unroll
        for (int j = 0; j < 4; j++) accG[i][j] = 0.f;
    float sq = 0.f;                  // this thread's channel sum-of-squares slice

    #pragma unroll 1
    for (int r = 0; r < ROWS_PC; r++) {
        const int y = chunk * ROWS_PC + r;
        __syncthreads();
        #pragma unroll
        for (int i = 0; i < 8; i++) {
            const int x0 = (grp + 8 * i) * 4;
            float o[4];
            conv4(plane, w, y, x0, o);
            dst[x0 + 0] = o[0];  dst[x0 + 1] = o[1];
            dst[x0 + 2] = o[2];  dst[x0 + 3] = o[3];
            sq += o[0] * o[0] + o[1] * o[1] + o[2] * o[2] + o[3] * o[3];
        }
        __syncthreads();

        const float* qbase = qs + 4 * ti * GP + nbase;
        const float* kbase = ks + 4 * tj * GP + nbase;
        #pragma unroll 4
        for (int n = 0; n < 32; n++) {
            float qv[4], kv[4];
            #pragma unroll
            for (int i = 0; i < 4; i++) qv[i] = qbase[i * GP + n];
            #pragma unroll
            for (int j = 0; j < 4; j++) kv[j] = kbase[j * GP + n];
            #pragma unroll
            for (int i = 0; i < 4; i++)
                #pragma unroll
                for (int j = 0; j < 4; j++)
                    accG[i][j] += qv[i] * kv[j];
        }
    }

    // reduce gram partials across the 8 groups via smem (reuse tile area)
    __syncthreads();
    #pragma unroll
    for (int i = 0; i < 4; i++)
        #pragma unroll
        for (int j = 0; j < 4; j++)
            sm[g * 1024 + (4 * ti + i) * 32 + (4 * tj + j)] = accG[i][j];
    __syncthreads();

    #pragma unroll
    for (int o = 0; o < 2; o++) {
        const int out = tid + 512 * o;
        float s = 0.f;
        #pragma unroll
        for (int gg = 0; gg < 8; gg++) s += sm[gg * 1024 + out];
        g_gram_part[(long)chunk * (BATCH*NHEADS*HD*HD) + bh * 1024 + out] = s;
    }

    // sum-squares: reduce over the 8 x-group lanes (tid bits 0..2)
    sq += __shfl_xor_sync(0xffffffffu, sq, 1);
    sq += __shfl_xor_sync(0xffffffffu, sq, 2);
    sq += __shfl_xor_sync(0xffffffffu, sq, 4);
    if (grp == 0) {
        if (ch6 < 32)
            g_qsq_part[chunk * (BATCH*NHEADS*HD) + bh * HD + c] = sq;
        else
            g_ksq_part[chunk * (BATCH*NHEADS*HD) + bh * HD + c] = sq;
    }
}

// ---------------------------------------------------------------------------
// Depthwise conv for v channels -> split bf16 hi/lo in [b][ch][px] layout.
// ---------------------------------------------------------------------------
__global__ __launch_bounds__(256) void dwv(
    const float* __restrict__ qkv, const float* __restrict__ wdw)
{
    const long idx = (long)blockIdx.x * 256 + threadIdx.x;   // < 2*192*16384
    const int px0   = (int)(idx & 16383) << 2;
    const int plane = (int)(idx >> 14);                      // b*192 + ch
    const int ch = plane % KDIM, b = plane / KDIM;
    const int gch = 2 * C_ + ch;

    const float* in = qkv + ((long)b * C3 + gch) * HW_;
    float w[9];
    #pragma unroll
    for (int i = 0; i < 9; i++) w[i] = wdw[gch * 9 + i];

    const int y  = px0 >> 8;
    const int x0 = px0 & 255;
    float o[4];
    conv4(in, w, y, x0, o);

    const long off = (long)plane * HW_ + px0;
    const __nv_bfloat16 h0 = __float2bfloat16(o[0]);
    const __nv_bfloat16 h1 = __float2bfloat16(o[1]);
    const __nv_bfloat16 h2 = __float2bfloat16(o[2]);
    const __nv_bfloat16 h3 = __float2bfloat16(o[3]);
    *reinterpret_cast<__nv_bfloat162*>(g_v_h + off)     = __nv_bfloat162(h0, h1);
    *reinterpret_cast<__nv_bfloat162*>(g_v_h + off + 2) = __nv_bfloat162(h2, h3);
    *reinterpret_cast<__nv_bfloat162*>(g_v_l + off) =
        __nv_bfloat162(__float2bfloat16(o[0] - __bfloat162float(h0)),
                       __float2bfloat16(o[1] - __bfloat162float(h1)));
    *reinterpret_cast<__nv_bfloat162*>(g_v_l + off + 2) =
        __nv_bfloat162(__float2bfloat16(o[2] - __bfloat162float(h2)),
                       __float2bfloat16(o[3] - __bfloat162float(h3)));
}

// split x (fp32 [b][192][HW]) -> hi/lo bf16, same layout
__global__ __launch_bounds__(256) void split_x(const float* __restrict__ x)
{
    const long idx = (long)blockIdx.x * 256 + threadIdx.x;
    const long off = idx * 4;
    const float4 f = *reinterpret_cast<const float4*>(x + off);
    const __nv_bfloat16 h0 = __float2bfloat16(f.x);
    const __nv_bfloat16 h1 = __float2bfloat16(f.y);
    const __nv_bfloat16 h2 = __float2bfloat16(f.z);
    const __nv_bfloat16 h3 = __float2bfloat16(f.w);
    *reinterpret_cast<__nv_bfloat162*>(g_x_h + off)     = __nv_bfloat162(h0, h1);
    *reinterpret_cast<__nv_bfloat162*>(g_x_h + off + 2) = __nv_bfloat162(h2, h3);
    *reinterpret_cast<__nv_bfloat162*>(g_x_l + off) =
        __nv_bfloat162(__float2bfloat16(f.x - __bfloat162float(h0)),
                       __float2bfloat16(f.y - __bfloat162float(h1)));
    *reinterpret_cast<__nv_bfloat162*>(g_x_l + off + 2) =
        __nv_bfloat162(__float2bfloat16(f.z - __bfloat162float(h2)),
                       __float2bfloat16(f.w - __bfloat162float(h3)));
}

// split w_qkv (576x192 fp32) -> A1 hi/lo (padded 640x192)
__global__ __launch_bounds__(256) void split_w1(const float* __restrict__ w)
{
    const int i = blockIdx.x * 256 + threadIdx.x;
    const float f = w[i];
    const __nv_bfloat16 h = __float2bfloat16(f);
    g_A1_h[i] = h;
    g_A1_l[i] = __float2bfloat16(f - __bfloat162float(h));
}

// reduce + normalize + temperature + softmax
__global__ __launch_bounds__(1024) void attn_kernel(const float* __restrict__ temperature)
{
    const int bh = blockIdx.x;
    const int h = bh % NHEADS;
    const int e = threadIdx.x, d = threadIdx.y;

    float g = 0.f, qsq = 0.f, ksq = 0.f;
    #pragma unroll
    for (int ch = 0; ch < GR_CHUNKS; ch++) {
        g   += g_gram_part[(long)ch * (BATCH*NHEADS*HD*HD) + bh * 1024 + d * 32 + e];
        qsq += g_qsq_part[ch * (BATCH*NHEADS*HD) + bh * HD + d];
        ksq += g_ksq_part[ch * (BATCH*NHEADS*HD) + bh * HD + e];
    }
    const float t  = fminf(temperature[h], 5.0f);
    const float qn = fmaxf(sqrtf(qsq), 1e-12f);
    const float kn = fmaxf(sqrtf(ksq), 1e-12f);
    const float val = g / (qn * kn) * t;

    float m = val;
    #pragma unroll
    for (int o = 16; o > 0; o >>= 1) m = fmaxf(m, __shfl_xor_sync(0xffffffffu, m, o));
    const float p = expf(val - m);
    float s = p;
    #pragma unroll
    for (int o = 16; o > 0; o >>= 1) s += __shfl_xor_sync(0xffffffffu, s, o);

    g_attn[bh * 1024 + d * 32 + e] = p / s;
}

// M_eff = w_proj @ blockdiag(attn) -> pre-split bf16 A2 (padded 256x192/batch)
__global__ __launch_bounds__(256) void meff_kernel(const float* __restrict__ wproj)
{
    const int idx = blockIdx.x * 256 + threadIdx.x;
    const int bz  = blockIdx.y;
    const int o   = idx / C_;
    const int ce  = idx % C_;
    const int h   = ce >> 5, e = ce & 31;

    const float* ar = g_attn + (bz * NHEADS + h) * 1024 + e;
    const float* wr = wproj + o * C_ + h * 32;

    float s = 0.f;
    #pragma unroll
    for (int dd = 0; dd < 32; dd++) s += wr[dd] * ar[dd * 32];

    const __nv_bfloat16 hi = __float2bfloat16(s);
    const long oidx = (long)bz * M2PAD * KDIM + (long)o * KDIM + ce;
    g_A2_h[oidx] = hi;
    g_A2_l[oidx] = __float2bfloat16(s - __bfloat162float(hi));
}

// ---------------------------------------------------------------------------
extern "C" void kernel_launch(void* const* d_in, const int* in_sizes, int n_in,
                              void* d_out, int out_size)
{
    (void)in_sizes; (void)n_in; (void)out_size;
    const float* x      = (const float*)d_in[0];
    const float* w_qkv  = (const float*)d_in[1];
    const float* w_dw   = (const float*)d_in[2];
    const float* w_proj = (const float*)d_in[3];
    const float* temp   = (const float*)d_in[4];
    float* out = (float*)d_out;

    float *qkv;
    __nv_bfloat16 *xh, *xl, *vh, *vl, *a1h, *a1l, *a2h, *a2l;
    cudaGetSymbolAddress((void**)&qkv, g_qkv);
    cudaGetSymbolAddress((void**)&xh, g_x_h);
    cudaGetSymbolAddress((void**)&xl, g_x_l);
    cudaGetSymbolAddress((void**)&vh, g_v_h);
    cudaGetSymbolAddress((void**)&vl, g_v_l);
    cudaGetSymbolAddress((void**)&a1h, g_A1_h);
    cudaGetSymbolAddress((void**)&a1l, g_A1_l);
    cudaGetSymbolAddress((void**)&a2h, g_A2_h);
    cudaGetSymbolAddress((void**)&a2l, g_A2_l);

    static bool attr_set = false;
    if (!attr_set) {
        cudaFuncSetAttribute(gemm_mma, cudaFuncAttributeMaxDynamicSharedMemorySize, GSMEM);
        cudaFuncSetAttribute(dwgram,   cudaFuncAttributeMaxDynamicSharedMemorySize, DG_SMEM);
        attr_set = true;
    }

    // 0) split weights + x
    split_w1<<<(M1 * KDIM) / 256, 256>>>(w_qkv);
    split_x<<<(int)(((long)BATCH * KDIM * HW_ / 4) / 256), 256>>>(x);

    // 1) qkv = w_qkv @ x
    gemm_mma<<<dim3(M1PAD / BM, HW_ / BN, BATCH), 256, GSMEM>>>(
        a1h, a1l, xh, xl, qkv, M1, 0L, (long)C3 * HW_);

    // 2) fused depthwise conv + gram partials (q,k)
    dwgram<<<dim3(GR_CHUNKS, BATCH * NHEADS), 512, DG_SMEM>>>(qkv, w_dw);

    // 3) depthwise conv v -> split bf16 [K][N]
    dwv<<<(int)(((long)BATCH * KDIM * HW_ / 4) / 256), 256>>>(qkv, w_dw);

    // 4) softmax + proj-absorb
    attn_kernel<<<BATCH * NHEADS, dim3(32, 32)>>>(temp);
    meff_kernel<<<dim3((C_ * C_) / 256, BATCH), 256>>>(w_proj);

    // 5) out = M_eff @ v
    gemm_mma<<<dim3(M2PAD / BM, HW_ / BN, BATCH), 256, GSMEM>>>(
        a2h, a2l, vh, vl, out, M2, (long)M2PAD * KDIM, (long)C_ * HW_);
}

// round 8
// speedup vs baseline: 2.5950x; 1.0307x over previous
#include <cuda_runtime.h>
#include <cuda_bf16.h>
#include <cstdint>

#define C_     192
#define C3     576
#define NHEADS 6
#define HD     32
#define HH_    256
#define WW_    256
#define HW_    65536
#define BATCH  2
#define KDIM   192
#define M1     576
#define M1PAD  640
#define M2     192
#define M2PAD  256

#define GR_CHUNKS 64           // 64 chunks x 4 rows = 256 image rows
#define ROWS_PC   4

// GEMM tiling (single pass: Ah,Al,Bh,Bl all resident per k-tile)
#define BM 128
#define BN 128
#define BK 32
#define APITCH 80              // bytes per A smem row (64B data + 16B pad)
#define BPITCH 272             // bytes per B smem row (256B data + 16B pad)
#define ATILE (BM * APITCH)    // 10240
#define BTILE (BK * BPITCH)    // 8704
#define BUFSZ (2 * ATILE + 2 * BTILE)  // 37888
#define GSMEM (2 * BUFSZ)              // 75776
#define NITER 6                        // 192/32 k-tiles, one pass

// dwgram tiles: 4 bf16 tiles [32ch][256px], pitch 528B (16B-chunk stride 33 -> conflict-free)
#define QP_B 528
#define DG_SMEM (4 * 32 * QP_B)        // 67584 B

// ---------------- scratch (device globals) -----------------------------------
__device__ float g_qkv[BATCH * C3 * HW_];
__device__ __nv_bfloat16 g_x_h[BATCH * KDIM * HW_];   // [b][k][n]
__device__ __nv_bfloat16 g_x_l[BATCH * KDIM * HW_];
__device__ __nv_bfloat16 g_v_h[BATCH * KDIM * HW_];
__device__ __nv_bfloat16 g_v_l[BATCH * KDIM * HW_];
__device__ __nv_bfloat16 g_A1_h[M1PAD * KDIM];        // padded rows stay zero
__device__ __nv_bfloat16 g_A1_l[M1PAD * KDIM];
__device__ __nv_bfloat16 g_A2_h[BATCH * M2PAD * KDIM];
__device__ __nv_bfloat16 g_A2_l[BATCH * M2PAD * KDIM];
__device__ float g_gram_part[GR_CHUNKS * BATCH * NHEADS * HD * HD];
__device__ float g_qsq_part [GR_CHUNKS * BATCH * NHEADS * HD];
__device__ float g_ksq_part [GR_CHUNKS * BATCH * NHEADS * HD];
__device__ float g_attn[BATCH * NHEADS * HD * HD];

// ---------------- PTX helpers (sm_80+ only) ----------------------------------
__device__ __forceinline__ uint32_t smem_u32(const void* p) {
    uint32_t a;
    asm("{ .reg .u64 t; cvta.to.shared.u64 t, %1; cvt.u32.u64 %0, t; }" : "=r"(a) : "l"(p));
    return a;
}
#define CP_ASYNC16(dst, src) \
    asm volatile("cp.async.cg.shared.global [%0], [%1], 16;" :: "r"(dst), "l"(src))
#define CP_COMMIT() asm volatile("cp.async.commit_group;" ::: "memory")
#define CP_WAIT(n)  asm volatile("cp.async.wait_group %0;" :: "n"(n) : "memory")

#define LDM_X4(r, addr) \
    asm volatile("ldmatrix.sync.aligned.m8n8.x4.shared.b16 {%0,%1,%2,%3}, [%4];" \
        : "=r"((r)[0]), "=r"((r)[1]), "=r"((r)[2]), "=r"((r)[3]) : "r"(addr))
#define LDM_X2T(r, addr) \
    asm volatile("ldmatrix.sync.aligned.m8n8.x2.trans.shared.b16 {%0,%1}, [%2];" \
        : "=r"((r)[0]), "=r"((r)[1]) : "r"(addr))

__device__ __forceinline__ void mma16816(float* d, const uint32_t* a, const uint32_t* b) {
    asm volatile(
        "mma.sync.aligned.m16n8k16.row.col.f32.bf16.bf16.f32 "
        "{%0,%1,%2,%3}, {%4,%5,%6,%7}, {%8,%9}, {%0,%1,%2,%3};"
        : "+f"(d[0]), "+f"(d[1]), "+f"(d[2]), "+f"(d[3])
        : "r"(a[0]), "r"(a[1]), "r"(a[2]), "r"(a[3]), "r"(b[0]), "r"(b[1]));
}

// ---------------------------------------------------------------------------
// Single-pass split-bf16 GEMM: C = A*B, A[M][192] hi/lo, B[192][HW] hi/lo.
// ---------------------------------------------------------------------------
__global__ __launch_bounds__(256, 2) void gemm_mma(
    const __nv_bfloat16* __restrict__ Ah, const __nv_bfloat16* __restrict__ Al,
    const __nv_bfloat16* __restrict__ Bh, const __nv_bfloat16* __restrict__ Bl,
    float* __restrict__ C, int Mvalid, long aBatch, long cBatch)
{
    extern __shared__ char smem[];
    const uint32_t sb = smem_u32(smem);

    const int tid  = threadIdx.x;
    const int wid  = tid >> 5;
    const int lane = tid & 31;
    const int wm   = wid >> 2;       // 0..1  (64 rows)
    const int wn   = wid & 3;        // 0..3  (32 cols)

    const int bz = blockIdx.z;
    const int m0 = blockIdx.x * BM;
    const int n0 = blockIdx.y * BN;

    Ah += (long)bz * aBatch;  Al += (long)bz * aBatch;
    Bh += (long)bz * KDIM * HW_;  Bl += (long)bz * KDIM * HW_;
    C  += (long)bz * cBatch;

    float acc[4][4][4];
    #pragma unroll
    for (int i = 0; i < 4; i++)
        #pragma unroll
        for (int j = 0; j < 4; j++)
            #pragma unroll
            for (int r = 0; r < 4; r++) acc[i][j][r] = 0.f;

    auto loadTiles = [&](int it, int buf) {
        const int k0 = it * BK;
        const uint32_t base = sb + (uint32_t)buf * BUFSZ;
        #pragma unroll
        for (int i = 0; i < 2; i++) {
            const int ca = tid + 256 * i;          // 0..511
            const int ar = ca >> 2, as_ = ca & 3;
            const long goff = (long)(m0 + ar) * KDIM + k0 + as_ * 8;
            const uint32_t soff = ar * APITCH + as_ * 16;
            CP_ASYNC16(base + soff,          Ah + goff);
            CP_ASYNC16(base + ATILE + soff,  Al + goff);
            const int br = ca >> 4, bs_ = ca & 15;
            const long gob = (long)(k0 + br) * HW_ + n0 + bs_ * 8;
            const uint32_t sofb = br * BPITCH + bs_ * 16;
            CP_ASYNC16(base + 2 * ATILE + sofb,         Bh + gob);
            CP_ASYNC16(base + 2 * ATILE + BTILE + sofb, Bl + gob);
        }
    };

    loadTiles(0, 0);
    CP_COMMIT();

    #pragma unroll 1
    for (int it = 0; it < NITER; it++) {
        if (it + 1 < NITER) {
            loadTiles(it + 1, (it + 1) & 1);
            CP_COMMIT();
            CP_WAIT(1);
        } else {
            CP_WAIT(0);
        }
        __syncthreads();

        const uint32_t base  = sb + (uint32_t)(it & 1) * BUFSZ;
        const uint32_t aHb = base, aLb = base + ATILE;
        const uint32_t bHb = base + 2 * ATILE, bLb = bHb + BTILE;

        #pragma unroll
        for (int kf = 0; kf < 2; kf++) {
            uint32_t aH[4][4], aL[4][4], bH[4][2], bL[4][2];
            #pragma unroll
            for (int i = 0; i < 4; i++) {
                const uint32_t ro = (uint32_t)(wm * 64 + i * 16 + (lane & 15)) * APITCH
                                  + kf * 32 + ((lane >> 4) << 4);
                LDM_X4(aH[i], aHb + ro);
                LDM_X4(aL[i], aLb + ro);
            }
            #pragma unroll
            for (int j = 0; j < 4; j++) {
                const uint32_t ro = (uint32_t)(kf * 16 + (lane & 15)) * BPITCH
                                  + (uint32_t)(wn * 32 + j * 8) * 2;
                LDM_X2T(bH[j], bHb + ro);
                LDM_X2T(bL[j], bLb + ro);
            }
            #pragma unroll
            for (int i = 0; i < 4; i++)
                #pragma unroll
                for (int j = 0; j < 4; j++) {
                    mma16816(acc[i][j], aH[i], bH[j]);
                    mma16816(acc[i][j], aH[i], bL[j]);
                    mma16816(acc[i][j], aL[i], bH[j]);
                }
        }
        __syncthreads();
    }

    const int rw = m0 + wm * 64 + (lane >> 2);
    const int cw = n0 + wn * 32 + (lane & 3) * 2;
    #pragma unroll
    for (int i = 0; i < 4; i++) {
        #pragma unroll
        for (int j = 0; j < 4; j++) {
            const int row = rw + i * 16;
            const int col = cw + j * 8;
            if (row < Mvalid)
                *reinterpret_cast<float2*>(C + (long)row * HW_ + col) =
                    make_float2(acc[i][j][0], acc[i][j][1]);
            if (row + 8 < Mvalid)
                *reinterpret_cast<float2*>(C + (long)(row + 8) * HW_ + col) =
                    make_float2(acc[i][j][2], acc[i][j][3]);
        }
    }
}

// ---------------------------------------------------------------------------
// 4-pixel depthwise conv: rows y-1..y+1, x0..x0+3 (x0 % 4 == 0, x0 in [0,256))
// ---------------------------------------------------------------------------
__device__ __forceinline__ void conv4(
    const float* __restrict__ plane, const float* __restrict__ w,
    int y, int x0, float out[4])
{
    out[0] = out[1] = out[2] = out[3] = 0.f;
    #pragma unroll
    for (int dy = -1; dy <= 1; dy++) {
        const int yy = y + dy;
        if (yy < 0 || yy >= HH_) continue;
        const float* row = plane + yy * WW_ + x0;
        const float4 m = *reinterpret_cast<const float4*>(row);
        const float lft = (x0 > 0)       ? row[-1] : 0.f;
        const float rgt = (x0 + 4 < 256) ? row[4]  : 0.f;
        const float w0 = w[(dy + 1) * 3 + 0];
        const float w1 = w[(dy + 1) * 3 + 1];
        const float w2 = w[(dy + 1) * 3 + 2];
        out[0] += w0 * lft + w1 * m.x + w2 * m.y;
        out[1] += w0 * m.x + w1 * m.y + w2 * m.z;
        out[2] += w0 * m.y + w1 * m.z + w2 * m.w;
        out[3] += w0 * m.z + w1 * m.w + w2 * rgt;
    }
}

// ---------------------------------------------------------------------------
// Fused depthwise conv (q,k) + TENSOR-CORE Gram partials.
// Conv writes split hi/lo bf16 into 4 smem tiles; gram = mma.sync bf16 with
// 3-product hi/lo split. 16 warps: warp w -> row-half (w>>3), 32-px slice (w&7).
// Sum-squares from fp32 conv registers (xor-shuffle over 8 x-group lanes).
// ---------------------------------------------------------------------------
__global__ __launch_bounds__(512, 2) void dwgram(
    const float* __restrict__ qkv, const float* __restrict__ wdw)
{
    extern __shared__ char smraw[];
    const uint32_t sb = smem_u32(smraw);
    const uint32_t qhb = sb;
    const uint32_t qlb = sb + 32 * QP_B;
    const uint32_t khb = sb + 2 * 32 * QP_B;
    const uint32_t klb = sb + 3 * 32 * QP_B;
    float* red = reinterpret_cast<float*>(smraw);   // reused after last mma

    const int bh = blockIdx.y;
    const int b = bh / NHEADS, h = bh % NHEADS;
    const int chunk = blockIdx.x;
    const int tid = threadIdx.x;
    const int lane = tid & 31;

    // conv mapping: 64 channels x 8 x-groups
    const int ch6 = tid >> 3;        // 0..63: <32 => q, else k
    const int grp = tid & 7;
    const int c   = ch6 & 31;
    const int gch = (ch6 < 32) ? (h * HD + c) : (C_ + h * HD + c);
    const float* plane = qkv + ((long)b * C3 + gch) * HW_;
    float w[9];
    #pragma unroll
    for (int i = 0; i < 9; i++) w[i] = wdw[gch * 9 + i];
    const uint32_t dstH = (ch6 < 32 ? qhb : khb) + (uint32_t)c * QP_B;
    const uint32_t dstL = (ch6 < 32 ? qlb : klb) + (uint32_t)c * QP_B;

    // gram warp mapping
    const int wrp  = tid >> 5;       // 0..15
    const int half = wrp >> 3;       // 0..1 -> q rows 16*half..
    const int slc  = wrp & 7;        // 0..7 -> pixels 32*slc..

    float acc[4][4];                 // 4 n-tiles x 4 regs: 16x32 partial
    #pragma unroll
    for (int j = 0; j < 4; j++)
        #pragma unroll
        for (int r = 0; r < 4; r++) acc[j][r] = 0.f;
    float sq = 0.f;

    #pragma unroll 1
    for (int r = 0; r < ROWS_PC; r++) {
        const int y = chunk * ROWS_PC + r;
        __syncthreads();
        #pragma unroll
        for (int i = 0; i < 8; i++) {
            const int x0 = (grp + 8 * i) * 4;
            float o[4];
            conv4(plane, w, y, x0, o);
            sq += o[0]*o[0] + o[1]*o[1] + o[2]*o[2] + o[3]*o[3];
            const __nv_bfloat16 h0 = __float2bfloat16(o[0]);
            const __nv_bfloat16 h1 = __float2bfloat16(o[1]);
            const __nv_bfloat16 h2 = __float2bfloat16(o[2]);
            const __nv_bfloat16 h3 = __float2bfloat16(o[3]);
            uint2 ph, pl;
            __nv_bfloat162 t0(h0, h1), t1(h2, h3);
            ph.x = *reinterpret_cast<uint32_t*>(&t0);
            ph.y = *reinterpret_cast<uint32_t*>(&t1);
            __nv_bfloat162 u0(__float2bfloat16(o[0] - __bfloat162float(h0)),
                              __float2bfloat16(o[1] - __bfloat162float(h1)));
            __nv_bfloat162 u1(__float2bfloat16(o[2] - __bfloat162float(h2)),
                              __float2bfloat16(o[3] - __bfloat162float(h3)));
            pl.x = *reinterpret_cast<uint32_t*>(&u0);
            pl.y = *reinterpret_cast<uint32_t*>(&u1);
            *reinterpret_cast<uint2*>(smraw + (dstH - sb) + x0 * 2) = ph;
            *reinterpret_cast<uint2*>(smraw + (dstL - sb) + x0 * 2) = pl;
        }
        __syncthreads();

        // gram mma over this row's 256 px: warp handles 32-px slice
        #pragma unroll
        for (int c2 = 0; c2 < 2; c2++) {
            const uint32_t off = (uint32_t)(slc * 64 + c2 * 32);  // bytes
            uint32_t aH[4], aL[4], bH[2][4], bL[2][4];
            const uint32_t ra = (uint32_t)(16 * half + (lane & 15)) * QP_B
                              + ((lane >> 4) << 4) + off;
            LDM_X4(aH, qhb + ra);
            LDM_X4(aL, qlb + ra);
            #pragma unroll
            for (int nt2 = 0; nt2 < 2; nt2++) {
                const uint32_t rb = (uint32_t)((lane & 7) + ((lane >> 4) << 3) + 16 * nt2) * QP_B
                                  + (((lane >> 3) & 1) << 4) + off;
                LDM_X4(bH[nt2], khb + rb);
                LDM_X4(bL[nt2], klb + rb);
            }
            #pragma unroll
            for (int nt = 0; nt < 4; nt++) {
                const uint32_t* bh_ = &bH[nt >> 1][(nt & 1) * 2];
                const uint32_t* bl_ = &bL[nt >> 1][(nt & 1) * 2];
                mma16816(acc[nt], aH, bh_);
                mma16816(acc[nt], aH, bl_);
                mma16816(acc[nt], aL, bh_);
            }
        }
    }

    // reduce 16 warp-partials (each 16x32) -> 32x32
    __syncthreads();
    #pragma unroll
    for (int nt = 0; nt < 4; nt++) {
        #pragma unroll
        for (int rr = 0; rr < 4; rr++) {
            const int lr  = (lane >> 2) + ((rr >> 1) << 3);   // 0..15
            const int col = nt * 8 + (lane & 3) * 2 + (rr & 1);
            red[wrp * 512 + lr * 32 + col] = acc[nt][rr];
        }
    }
    __syncthreads();

    #pragma unroll
    for (int o = 0; o < 2; o++) {
        const int out = tid + 512 * o;         // 0..1023
        const int d = out >> 5, e = out & 31;
        const int hh = d >> 4, lr = d & 15;
        float s = 0.f;
        #pragma unroll
        for (int ww = 0; ww < 8; ww++)
            s += red[(8 * hh + ww) * 512 + lr * 32 + e];
        g_gram_part[(long)chunk * (BATCH*NHEADS*HD*HD) + bh * 1024 + out] = s;
    }

    // sum-squares: reduce over the 8 x-group lanes (tid bits 0..2)
    sq += __shfl_xor_sync(0xffffffffu, sq, 1);
    sq += __shfl_xor_sync(0xffffffffu, sq, 2);
    sq += __shfl_xor_sync(0xffffffffu, sq, 4);
    if (grp == 0) {
        if (ch6 < 32)
            g_qsq_part[chunk * (BATCH*NHEADS*HD) + bh * HD + c] = sq;
        else
            g_ksq_part[chunk * (BATCH*NHEADS*HD) + bh * HD + c] = sq;
    }
}

// ---------------------------------------------------------------------------
// Depthwise conv for v channels -> split bf16 hi/lo in [b][ch][px] layout.
// ---------------------------------------------------------------------------
__global__ __launch_bounds__(256) void dwv(
    const float* __restrict__ qkv, const float* __restrict__ wdw)
{
    const long idx = (long)blockIdx.x * 256 + threadIdx.x;   // < 2*192*16384
    const int px0   = (int)(idx & 16383) << 2;
    const int plane = (int)(idx >> 14);                      // b*192 + ch
    const int ch = plane % KDIM, b = plane / KDIM;
    const int gch = 2 * C_ + ch;

    const float* in = qkv + ((long)b * C3 + gch) * HW_;
    float w[9];
    #pragma unroll
    for (int i = 0; i < 9; i++) w[i] = wdw[gch * 9 + i];

    const int y  = px0 >> 8;
    const int x0 = px0 & 255;
    float o[4];
    conv4(in, w, y, x0, o);

    const long off = (long)plane * HW_ + px0;
    const __nv_bfloat16 h0 = __float2bfloat16(o[0]);
    const __nv_bfloat16 h1 = __float2bfloat16(o[1]);
    const __nv_bfloat16 h2 = __float2bfloat16(o[2]);
    const __nv_bfloat16 h3 = __float2bfloat16(o[3]);
    *reinterpret_cast<__nv_bfloat162*>(g_v_h + off)     = __nv_bfloat162(h0, h1);
    *reinterpret_cast<__nv_bfloat162*>(g_v_h + off + 2) = __nv_bfloat162(h2, h3);
    *reinterpret_cast<__nv_bfloat162*>(g_v_l + off) =
        __nv_bfloat162(__float2bfloat16(o[0] - __bfloat162float(h0)),
                       __float2bfloat16(o[1] - __bfloat162float(h1)));
    *reinterpret_cast<__nv_bfloat162*>(g_v_l + off + 2) =
        __nv_bfloat162(__float2bfloat16(o[2] - __bfloat162float(h2)),
                       __float2bfloat16(o[3] - __bfloat162float(h3)));
}

// split x (fp32 [b][192][HW]) -> hi/lo bf16, same layout
__global__ __launch_bounds__(256) void split_x(const float* __restrict__ x)
{
    const long idx = (long)blockIdx.x * 256 + threadIdx.x;
    const long off = idx * 4;
    const float4 f = *reinterpret_cast<const float4*>(x + off);
    const __nv_bfloat16 h0 = __float2bfloat16(f.x);
    const __nv_bfloat16 h1 = __float2bfloat16(f.y);
    const __nv_bfloat16 h2 = __float2bfloat16(f.z);
    const __nv_bfloat16 h3 = __float2bfloat16(f.w);
    *reinterpret_cast<__nv_bfloat162*>(g_x_h + off)     = __nv_bfloat162(h0, h1);
    *reinterpret_cast<__nv_bfloat162*>(g_x_h + off + 2) = __nv_bfloat162(h2, h3);
    *reinterpret_cast<__nv_bfloat162*>(g_x_l + off) =
        __nv_bfloat162(__float2bfloat16(f.x - __bfloat162float(h0)),
                       __float2bfloat16(f.y - __bfloat162float(h1)));
    *reinterpret_cast<__nv_bfloat162*>(g_x_l + off + 2) =
        __nv_bfloat162(__float2bfloat16(f.z - __bfloat162float(h2)),
                       __float2bfloat16(f.w - __bfloat162float(h3)));
}

// split w_qkv (576x192 fp32) -> A1 hi/lo (padded 640x192)
__global__ __launch_bounds__(256) void split_w1(const float* __restrict__ w)
{
    const int i = blockIdx.x * 256 + threadIdx.x;
    const float f = w[i];
    const __nv_bfloat16 h = __float2bfloat16(f);
    g_A1_h[i] = h;
    g_A1_l[i] = __float2bfloat16(f - __bfloat162float(h));
}

// reduce + normalize + temperature + softmax
__global__ __launch_bounds__(1024) void attn_kernel(const float* __restrict__ temperature)
{
    const int bh = blockIdx.x;
    const int h = bh % NHEADS;
    const int e = threadIdx.x, d = threadIdx.y;

    float g = 0.f, qsq = 0.f, ksq = 0.f;
    #pragma unroll
    for (int ch = 0; ch < GR_CHUNKS; ch++) {
        g   += g_gram_part[(long)ch * (BATCH*NHEADS*HD*HD) + bh * 1024 + d * 32 + e];
        qsq += g_qsq_part[ch * (BATCH*NHEADS*HD) + bh * HD + d];
        ksq += g_ksq_part[ch * (BATCH*NHEADS*HD) + bh * HD + e];
    }
    const float t  = fminf(temperature[h], 5.0f);
    const float qn = fmaxf(sqrtf(qsq), 1e-12f);
    const float kn = fmaxf(sqrtf(ksq), 1e-12f);
    const float val = g / (qn * kn) * t;

    float m = val;
    #pragma unroll
    for (int o = 16; o > 0; o >>= 1) m = fmaxf(m, __shfl_xor_sync(0xffffffffu, m, o));
    const float p = expf(val - m);
    float s = p;
    #pragma unroll
    for (int o = 16; o > 0; o >>= 1) s += __shfl_xor_sync(0xffffffffu, s, o);

    g_attn[bh * 1024 + d * 32 + e] = p / s;
}

// M_eff = w_proj @ blockdiag(attn) -> pre-split bf16 A2 (padded 256x192/batch)
__global__ __launch_bounds__(256) void meff_kernel(const float* __restrict__ wproj)
{
    const int idx = blockIdx.x * 256 + threadIdx.x;
    const int bz  = blockIdx.y;
    const int o   = idx / C_;
    const int ce  = idx % C_;
    const int h   = ce >> 5, e = ce & 31;

    const float* ar = g_attn + (bz * NHEADS + h) * 1024 + e;
    const float* wr = wproj + o * C_ + h * 32;

    float s = 0.f;
    #pragma unroll
    for (int dd = 0; dd < 32; dd++) s += wr[dd] * ar[dd * 32];

    const __nv_bfloat16 hi = __float2bfloat16(s);
    const long oidx = (long)bz * M2PAD * KDIM + (long)o * KDIM + ce;
    g_A2_h[oidx] = hi;
    g_A2_l[oidx] = __float2bfloat16(s - __bfloat162float(hi));
}

// ---------------------------------------------------------------------------
extern "C" void kernel_launch(void* const* d_in, const int* in_sizes, int n_in,
                              void* d_out, int out_size)
{
    (void)in_sizes; (void)n_in; (void)out_size;
    const float* x      = (const float*)d_in[0];
    const float* w_qkv  = (const float*)d_in[1];
    const float* w_dw   = (const float*)d_in[2];
    const float* w_proj = (const float*)d_in[3];
    const float* temp   = (const float*)d_in[4];
    float* out = (float*)d_out;

    float *qkv;
    __nv_bfloat16 *xh, *xl, *vh, *vl, *a1h, *a1l, *a2h, *a2l;
    cudaGetSymbolAddress((void**)&qkv, g_qkv);
    cudaGetSymbolAddress((void**)&xh, g_x_h);
    cudaGetSymbolAddress((void**)&xl, g_x_l);
    cudaGetSymbolAddress((void**)&vh, g_v_h);
    cudaGetSymbolAddress((void**)&vl, g_v_l);
    cudaGetSymbolAddress((void**)&a1h, g_A1_h);
    cudaGetSymbolAddress((void**)&a1l, g_A1_l);
    cudaGetSymbolAddress((void**)&a2h, g_A2_h);
    cudaGetSymbolAddress((void**)&a2l, g_A2_l);

    static bool attr_set = false;
    if (!attr_set) {
        cudaFuncSetAttribute(gemm_mma, cudaFuncAttributeMaxDynamicSharedMemorySize, GSMEM);
        cudaFuncSetAttribute(dwgram,   cudaFuncAttributeMaxDynamicSharedMemorySize, DG_SMEM);
        attr_set = true;
    }

    // 0) split weights + x
    split_w1<<<(M1 * KDIM) / 256, 256>>>(w_qkv);
    split_x<<<(int)(((long)BATCH * KDIM * HW_ / 4) / 256), 256>>>(x);

    // 1) qkv = w_qkv @ x
    gemm_mma<<<dim3(M1PAD / BM, HW_ / BN, BATCH), 256, GSMEM>>>(
        a1h, a1l, xh, xl, qkv, M1, 0L, (long)C3 * HW_);

    // 2) fused depthwise conv + tensor-core gram partials (q,k)
    dwgram<<<dim3(GR_CHUNKS, BATCH * NHEADS), 512, DG_SMEM>>>(qkv, w_dw);

    // 3) depthwise conv v -> split bf16 [K][N]
    dwv<<<(int)(((long)BATCH * KDIM * HW_ / 4) / 256), 256>>>(qkv, w_dw);

    // 4) softmax + proj-absorb
    attn_kernel<<<BATCH * NHEADS, dim3(32, 32)>>>(temp);
    meff_kernel<<<dim3((C_ * C_) / 256, BATCH), 256>>>(w_proj);

    // 5) out = M_eff @ v
    gemm_mma<<<dim3(M2PAD / BM, HW_ / BN, BATCH), 256, GSMEM>>>(
        a2h, a2l, vh, vl, out, M2, (long)M2PAD * KDIM, (long)C_ * HW_);
}